// round 9
// baseline (speedup 1.0000x reference)
#include <cuda_runtime.h>
#include <cuda_bf16.h>
#include <cstdint>
#include <math.h>

#define B_  64
#define T_  256
#define C_  256
#define H_  8
#define HS_ 32
#define L_  6
#define V_  96
#define BT_ (B_ * T_)
#define EPS_ 1e-5f
#define WMAT 65536

// ---------------- scratch ----------------
__device__ __align__(16) float g_x  [BT_ * C_];
__device__ __align__(16) float g_qkv[3 * BT_ * C_];
__device__ __align__(16) float g_att[BT_ * C_];
__device__ __align__(16) float g_nll[BT_];
__device__ __align__(16) float g_sx [BT_];
__device__ __align__(16) float g_sh [BT_];
__device__ __align__(16) float g_sa [BT_];
__device__ __align__(16) int8_t g_x1[BT_ * C_];
__device__ __align__(16) int8_t g_x2[BT_ * C_];
__device__ __align__(16) int8_t g_h1[BT_ * C_];
__device__ __align__(16) int8_t g_h2[BT_ * C_];
__device__ __align__(16) int8_t g_a1[BT_ * C_];
__device__ __align__(16) int8_t g_a2[BT_ * C_];
#define WI_TOTAL (36 * WMAT + 128 * 256)
__device__ __align__(16) int8_t g_wi1[WI_TOTAL];
__device__ __align__(16) int8_t g_wi2[WI_TOTAL];
__device__ __align__(16) float  g_sw [36 * 256 + 128];

// ---------------- helpers ----------------
__device__ __forceinline__ uint32_t smem_u32(const void* p) {
    uint32_t a;
    asm("{ .reg .u64 t; cvta.to.shared.u64 t, %1; cvt.u32.u64 %0, t; }" : "=r"(a) : "l"(p));
    return a;
}
__device__ __forceinline__ void cp_async16(uint32_t dst, const void* src) {
    asm volatile("cp.async.cg.shared.global [%0], [%1], 16;" :: "r"(dst), "l"(src) : "memory");
}
__device__ __forceinline__ void cp_commit() { asm volatile("cp.async.commit_group;" ::: "memory"); }
template <int N>
__device__ __forceinline__ void cp_wait() {
    asm volatile("cp.async.wait_group %0;" :: "n"(N) : "memory");
}
__device__ __forceinline__ void ldmatrix_x4(uint32_t* r, uint32_t addr) {
    asm volatile("ldmatrix.sync.aligned.m8n8.x4.shared.b16 {%0,%1,%2,%3}, [%4];"
                 : "=r"(r[0]), "=r"(r[1]), "=r"(r[2]), "=r"(r[3]) : "r"(addr));
}
__device__ __forceinline__ void mma16816(float* c, const uint32_t* a, const uint32_t* b) {
    asm volatile("mma.sync.aligned.m16n8k16.row.col.f32.bf16.bf16.f32 "
                 "{%0,%1,%2,%3}, {%4,%5,%6,%7}, {%8,%9}, {%0,%1,%2,%3};"
                 : "+f"(c[0]), "+f"(c[1]), "+f"(c[2]), "+f"(c[3])
                 : "r"(a[0]), "r"(a[1]), "r"(a[2]), "r"(a[3]), "r"(b[0]), "r"(b[1]));
}
__device__ __forceinline__ void imma16832(int* c, const uint32_t* a, const uint32_t* b) {
    asm volatile("mma.sync.aligned.m16n8k32.row.col.s32.s8.s8.s32 "
                 "{%0,%1,%2,%3}, {%4,%5,%6,%7}, {%8,%9}, {%0,%1,%2,%3};"
                 : "+r"(c[0]), "+r"(c[1]), "+r"(c[2]), "+r"(c[3])
                 : "r"(a[0]), "r"(a[1]), "r"(a[2]), "r"(a[3]), "r"(b[0]), "r"(b[1]));
}
__device__ __forceinline__ uint32_t packbf2(float a, float b) {
    __nv_bfloat162 t(__float2bfloat16(a), __float2bfloat16(b));
    return *(uint32_t*)&t;
}
__device__ __forceinline__ void quant2f(float v, float s, float inv_s, int8_t& o1, int8_t& o2) {
    float f1 = fminf(fmaxf(rintf(v * inv_s), -127.f), 127.f);
    float f2 = fminf(fmaxf(rintf((v - s * f1) * inv_s * 128.f), -127.f), 127.f);
    o1 = (int8_t)(int)f1;
    o2 = (int8_t)(int)f2;
}
#define SWZ8(r, ch) ((r) * 64 + 16 * ((ch) ^ (((r) >> 1) & 3)))

// ---------------- weight convert: 2-digit int8 per output col --------------
__global__ void convw_all(const float* __restrict__ Wq, const float* __restrict__ Wk,
                          const float* __restrict__ Wv, const float* __restrict__ Wo,
                          const float* __restrict__ W1, const float* __restrict__ W2,
                          const float* __restrict__ Wlm,
                          int8_t* __restrict__ wi1, int8_t* __restrict__ wi2,
                          float* __restrict__ sw) {
    const int wrp = threadIdx.x >> 5, lane = threadIdx.x & 31;
    const int n = blockIdx.x * 8 + wrp, mat = blockIdx.y;
    float vals[8], mx = 0.f;
    size_t base;
    int sidx;
    if (mat < 36) {
        const float* srcs[6] = {Wq, Wk, Wv, Wo, W1, W2};
        const float* sp = srcs[mat / 6] + (size_t)(mat % 6) * WMAT;
#pragma unroll
        for (int ii = 0; ii < 8; ii++) {
            vals[ii] = sp[(size_t)(lane + 32 * ii) * 256 + n];
            mx = fmaxf(mx, fabsf(vals[ii]));
        }
        base = (size_t)mat * WMAT + (size_t)n * 256;
        sidx = mat * 256 + n;
    } else {
        if (n >= 128) return;
#pragma unroll
        for (int ii = 0; ii < 8; ii++) {
            vals[ii] = (n < V_) ? Wlm[(size_t)(lane + 32 * ii) * V_ + n] : 0.f;
            mx = fmaxf(mx, fabsf(vals[ii]));
        }
        base = (size_t)36 * WMAT + (size_t)n * 256;
        sidx = 36 * 256 + n;
    }
#pragma unroll
    for (int o = 16; o; o >>= 1) mx = fmaxf(mx, __shfl_xor_sync(0xffffffffu, mx, o));
    float s = fmaxf(mx, 1e-30f) * (1.f / 127.f), inv = 1.f / s;
#pragma unroll
    for (int ii = 0; ii < 8; ii++) {
        int8_t q1, q2;
        quant2f(vals[ii], s, inv, q1, q2);
        wi1[base + lane + 32 * ii] = q1;
        wi2[base + lane + 32 * ii] = q2;
    }
    if (lane == 0) sw[sidx] = s;
}

// ---------------- row quantize ----------------
__device__ __forceinline__ void rowquant_write(float v, int row, int c,
                                               int8_t* q1, int8_t* q2, float* sc) {
    __shared__ float sm8[8];
    float m = fabsf(v);
#pragma unroll
    for (int o = 16; o; o >>= 1) m = fmaxf(m, __shfl_xor_sync(0xffffffffu, m, o));
    if ((c & 31) == 0) sm8[c >> 5] = m;
    __syncthreads();
    float mx = 0.f;
#pragma unroll
    for (int i = 0; i < 8; i++) mx = fmaxf(mx, sm8[i]);
    float s = fmaxf(mx, 1e-30f) * (1.f / 127.f);
    int8_t a, b;
    quant2f(v, s, 1.f / s, a, b);
    size_t o = (size_t)row * 256 + c;
    q1[o] = a;
    q2[o] = b;
    if (c == 0) sc[row] = s;
}

__global__ void embed_kernel(const int* __restrict__ idx, const float* __restrict__ tok_emb,
                             const float* __restrict__ pos_emb, float* __restrict__ x,
                             int8_t* __restrict__ q1, int8_t* __restrict__ q2,
                             float* __restrict__ sc) {
    int bt = blockIdx.x, c = threadIdx.x;
    float v = tok_emb[idx[bt] * C_ + c] + pos_emb[(bt % T_) * C_ + c];
    x[(size_t)bt * C_ + c] = v;
    rowquant_write(v, bt, c, q1, q2, sc);
}

__global__ void quant_rows(const float* __restrict__ src, int8_t* __restrict__ q1,
                           int8_t* __restrict__ q2, float* __restrict__ sc) {
    rowquant_write(src[(size_t)blockIdx.x * 256 + threadIdx.x],
                   blockIdx.x, threadIdx.x, q1, q2, sc);
}

// ---------------- final LN -> int8 ----------------
__global__ void ln_quant(const float* __restrict__ x, const float* __restrict__ w,
                         const float* __restrict__ b, int8_t* __restrict__ q1,
                         int8_t* __restrict__ q2, float* __restrict__ sc) {
    const int row = blockIdx.x, c = threadIdx.x;
    float v = x[(size_t)row * C_ + c];
    float s = v, s2 = v * v;
    __shared__ float sh1[8], sh2[8];
#pragma unroll
    for (int o = 16; o; o >>= 1) {
        s  += __shfl_xor_sync(0xffffffffu, s, o);
        s2 += __shfl_xor_sync(0xffffffffu, s2, o);
    }
    if ((c & 31) == 0) { sh1[c >> 5] = s; sh2[c >> 5] = s2; }
    __syncthreads();
    float S = 0.f, Q = 0.f;
#pragma unroll
    for (int i = 0; i < 8; i++) { S += sh1[i]; Q += sh2[i]; }
    float mean = S * (1.f / C_);
    float var  = Q * (1.f / C_) - mean * mean;
    float r = (v - mean) * rsqrtf(var + EPS_) * w[c] + b[c];
    __syncthreads();
    rowquant_write(r, row, c, q1, q2, sc);
}

// ---------------- INT8 GEMM ----------------
// CTA 64 x NT rows, 256 thr, 8 warps (2M x 4N). 2-digit split both sides.
// MODE 0: fp32 (+bias) out. MODE 1: +bias relu -> int8+scale.
// MODE 2: +bias +res -> LN -> fp32 + int8+scale.
template <int NT, int MODE>
__global__ void __launch_bounds__(256)
i8_gemm(const int8_t* __restrict__ A1, const int8_t* __restrict__ A2,
        const float* __restrict__ sA,
        const int8_t* __restrict__ B1b, const int8_t* __restrict__ B2b,
        const float* __restrict__ sBb, size_t wstride,
        float* outF, size_t ostride,
        int8_t* __restrict__ q1o, int8_t* __restrict__ q2o, float* __restrict__ sOut,
        const float* __restrict__ bias, const float* __restrict__ res,
        const float* __restrict__ lnw, const float* __restrict__ lnb, int Nout) {
    extern __shared__ char smem[];
    const uint32_t sb = smem_u32(smem);
    constexpr int AO1 = 0, AO2 = 4096, BO1 = 8192, BO2 = 8192 + NT * 64;
    constexpr int STAGE = 8192 + 2 * NT * 64;
    constexpr int NCH = 512 + NT * 8;
    constexpr int WN = NT / 4, FJ = WN / 8, FJ2 = WN / 16;

    const int tid = threadIdx.x, lane = tid & 31, wrp = tid >> 5;
    const int wm = wrp & 1, wn = wrp >> 1;
    const size_t rowblock = (size_t)blockIdx.x * 64;
    const int8_t* B1 = B1b + blockIdx.y * wstride;
    const int8_t* B2 = B2b + blockIdx.y * wstride;
    const float*  sB = sBb + blockIdx.y * (wstride >> 8);
    if (MODE == 0) outF += blockIdx.y * ostride;

    int am[2][FJ][4], ac[2][FJ][4];
#pragma unroll
    for (int i = 0; i < 2; i++)
#pragma unroll
        for (int j = 0; j < FJ; j++)
#pragma unroll
            for (int r = 0; r < 4; r++) { am[i][j][r] = 0; ac[i][j][r] = 0; }

    auto load_stage = [&](int s, int buf) {
        const int k0 = s * 64;
        const uint32_t base = sb + buf * STAGE;
#pragma unroll
        for (int c = tid; c < NCH; c += 256) {
            int r, ch;
            if (c < 256) {
                r = c >> 2; ch = c & 3;
                cp_async16(base + AO1 + SWZ8(r, ch), A1 + (rowblock + r) * 256 + k0 + ch * 16);
            } else if (c < 512) {
                int cc = c - 256; r = cc >> 2; ch = cc & 3;
                cp_async16(base + AO2 + SWZ8(r, ch), A2 + (rowblock + r) * 256 + k0 + ch * 16);
            } else if (c < 512 + NT * 4) {
                int cc = c - 512; r = cc >> 2; ch = cc & 3;
                cp_async16(base + BO1 + SWZ8(r, ch), B1 + (size_t)r * 256 + k0 + ch * 16);
            } else {
                int cc = c - 512 - NT * 4; r = cc >> 2; ch = cc & 3;
                cp_async16(base + BO2 + SWZ8(r, ch), B2 + (size_t)r * 256 + k0 + ch * 16);
            }
        }
        cp_commit();
    };

    load_stage(0, 0);
    for (int s = 0; s < 4; s++) {
        if (s < 3) { load_stage(s + 1, (s + 1) & 1); cp_wait<1>(); }
        else       { cp_wait<0>(); }
        __syncthreads();
        const uint32_t base = sb + (s & 1) * STAGE;
#pragma unroll
        for (int ks = 0; ks < 2; ks++) {
            uint32_t a1f[2][4], a2f[2][4];
#pragma unroll
            for (int i = 0; i < 2; i++) {
                int r = wm * 32 + i * 16 + (lane & 15);
                int ch = 2 * ks + (lane >> 4);
                ldmatrix_x4(a1f[i], base + AO1 + SWZ8(r, ch));
                ldmatrix_x4(a2f[i], base + AO2 + SWZ8(r, ch));
            }
#pragma unroll
            for (int j2 = 0; j2 < FJ2; j2++) {
                int r = wn * WN + j2 * 16 + ((lane >> 4) & 1) * 8 + (lane & 7);
                int ch = 2 * ks + ((lane >> 3) & 1);
                uint32_t b1f[4], b2f[4];
                ldmatrix_x4(b1f, base + BO1 + SWZ8(r, ch));
                ldmatrix_x4(b2f, base + BO2 + SWZ8(r, ch));
#pragma unroll
                for (int i = 0; i < 2; i++) {
                    imma16832(am[i][2 * j2],     a1f[i], b1f);
                    imma16832(am[i][2 * j2 + 1], a1f[i], b1f + 2);
                    imma16832(ac[i][2 * j2],     a1f[i], b2f);
                    imma16832(ac[i][2 * j2 + 1], a1f[i], b2f + 2);
                    imma16832(ac[i][2 * j2],     a2f[i], b1f);
                    imma16832(ac[i][2 * j2 + 1], a2f[i], b1f + 2);
                }
            }
        }
        __syncthreads();
    }

    const int g = lane >> 2, tg = lane & 3;
    float sa[2][2];
#pragma unroll
    for (int i = 0; i < 2; i++) {
        sa[i][0] = sA[rowblock + wm * 32 + i * 16 + g];
        sa[i][1] = sA[rowblock + wm * 32 + i * 16 + g + 8];
    }
#pragma unroll
    for (int i = 0; i < 2; i++)
#pragma unroll
        for (int j = 0; j < FJ; j++) {
            int col = wn * WN + j * 8 + tg * 2;
            float t0 = sB[col], t1 = sB[col + 1];
            float b0 = 0.f, b1 = 0.f;
            if (MODE != 0) { b0 = bias[col]; b1 = bias[col + 1]; }
            else if (bias != nullptr && col + 1 < Nout) { b0 = bias[col]; b1 = bias[col + 1]; }
            float v00 = sa[i][0] * t0 * ((float)am[i][j][0] + 0.0078125f * (float)ac[i][j][0]) + b0;
            float v01 = sa[i][0] * t1 * ((float)am[i][j][1] + 0.0078125f * (float)ac[i][j][1]) + b1;
            float v10 = sa[i][1] * t0 * ((float)am[i][j][2] + 0.0078125f * (float)ac[i][j][2]) + b0;
            float v11 = sa[i][1] * t1 * ((float)am[i][j][3] + 0.0078125f * (float)ac[i][j][3]) + b1;
            if (MODE == 1) {
                v00 = fmaxf(v00, 0.f); v01 = fmaxf(v01, 0.f);
                v10 = fmaxf(v10, 0.f); v11 = fmaxf(v11, 0.f);
            }
            am[i][j][0] = __float_as_int(v00); am[i][j][1] = __float_as_int(v01);
            am[i][j][2] = __float_as_int(v10); am[i][j][3] = __float_as_int(v11);
        }

    if (MODE == 0) {
#pragma unroll
        for (int i = 0; i < 2; i++)
#pragma unroll
            for (int j = 0; j < FJ; j++) {
                int col = wn * WN + j * 8 + tg * 2;
                if (col + 1 >= Nout) continue;
                size_t r0 = rowblock + wm * 32 + i * 16 + g, r1 = r0 + 8;
                *(float2*)(outF + r0 * Nout + col) =
                    make_float2(__int_as_float(am[i][j][0]), __int_as_float(am[i][j][1]));
                *(float2*)(outF + r1 * Nout + col) =
                    make_float2(__int_as_float(am[i][j][2]), __int_as_float(am[i][j][3]));
            }
        return;
    }

    float* rs = (float*)smem;   // [64][4]
    float* rq = rs + 256;

    if (MODE == 2) {
        float vsum[2][2] = {{0.f, 0.f}, {0.f, 0.f}};
        float vsq [2][2] = {{0.f, 0.f}, {0.f, 0.f}};
#pragma unroll
        for (int i = 0; i < 2; i++)
#pragma unroll
            for (int j = 0; j < FJ; j++) {
                int col = wn * WN + j * 8 + tg * 2;
                size_t r0 = rowblock + wm * 32 + i * 16 + g, r1 = r0 + 8;
                float2 p0 = *(const float2*)(res + r0 * NT + col);
                float2 p1 = *(const float2*)(res + r1 * NT + col);
                float v00 = __int_as_float(am[i][j][0]) + p0.x;
                float v01 = __int_as_float(am[i][j][1]) + p0.y;
                float v10 = __int_as_float(am[i][j][2]) + p1.x;
                float v11 = __int_as_float(am[i][j][3]) + p1.y;
                am[i][j][0] = __float_as_int(v00); am[i][j][1] = __float_as_int(v01);
                am[i][j][2] = __float_as_int(v10); am[i][j][3] = __float_as_int(v11);
                vsum[i][0] += v00 + v01;  vsq[i][0] += v00 * v00 + v01 * v01;
                vsum[i][1] += v10 + v11;  vsq[i][1] += v10 * v10 + v11 * v11;
            }
#pragma unroll
        for (int i = 0; i < 2; i++)
#pragma unroll
            for (int hf = 0; hf < 2; hf++) {
                float s = vsum[i][hf], q = vsq[i][hf];
                s += __shfl_xor_sync(0xffffffffu, s, 1);
                s += __shfl_xor_sync(0xffffffffu, s, 2);
                q += __shfl_xor_sync(0xffffffffu, q, 1);
                q += __shfl_xor_sync(0xffffffffu, q, 2);
                if (tg == 0) {
                    int lr = wm * 32 + i * 16 + hf * 8 + g;
                    rs[lr * 4 + wn] = s;
                    rq[lr * 4 + wn] = q;
                }
            }
        __syncthreads();
        float mean[2][2], rstd[2][2];
#pragma unroll
        for (int i = 0; i < 2; i++)
#pragma unroll
            for (int hf = 0; hf < 2; hf++) {
                int lr = wm * 32 + i * 16 + hf * 8 + g;
                float S = rs[lr * 4] + rs[lr * 4 + 1] + rs[lr * 4 + 2] + rs[lr * 4 + 3];
                float Q = rq[lr * 4] + rq[lr * 4 + 1] + rq[lr * 4 + 2] + rq[lr * 4 + 3];
                float mn = S * (1.f / NT);
                mean[i][hf] = mn;
                rstd[i][hf] = rsqrtf(Q * (1.f / NT) - mn * mn + EPS_);
            }
        __syncthreads();
#pragma unroll
        for (int i = 0; i < 2; i++)
#pragma unroll
            for (int j = 0; j < FJ; j++) {
                int col = wn * WN + j * 8 + tg * 2;
                size_t r0 = rowblock + wm * 32 + i * 16 + g, r1 = r0 + 8;
                float w0 = lnw[col], w1 = lnw[col + 1];
                float c0 = lnb[col], c1 = lnb[col + 1];
                float v00 = (__int_as_float(am[i][j][0]) - mean[i][0]) * rstd[i][0] * w0 + c0;
                float v01 = (__int_as_float(am[i][j][1]) - mean[i][0]) * rstd[i][0] * w1 + c1;
                float v10 = (__int_as_float(am[i][j][2]) - mean[i][1]) * rstd[i][1] * w0 + c0;
                float v11 = (__int_as_float(am[i][j][3]) - mean[i][1]) * rstd[i][1] * w1 + c1;
                *(float2*)(outF + r0 * NT + col) = make_float2(v00, v01);
                *(float2*)(outF + r1 * NT + col) = make_float2(v10, v11);
                am[i][j][0] = __float_as_int(v00); am[i][j][1] = __float_as_int(v01);
                am[i][j][2] = __float_as_int(v10); am[i][j][3] = __float_as_int(v11);
            }
    }

    // rowmax -> scale -> quantize (MODE 1 & 2)
    float mx[2][2] = {{0.f, 0.f}, {0.f, 0.f}};
#pragma unroll
    for (int i = 0; i < 2; i++)
#pragma unroll
        for (int j = 0; j < FJ; j++) {
            mx[i][0] = fmaxf(mx[i][0], fmaxf(fabsf(__int_as_float(am[i][j][0])),
                                             fabsf(__int_as_float(am[i][j][1]))));
            mx[i][1] = fmaxf(mx[i][1], fmaxf(fabsf(__int_as_float(am[i][j][2])),
                                             fabsf(__int_as_float(am[i][j][3]))));
        }
    __syncthreads();
#pragma unroll
    for (int i = 0; i < 2; i++)
#pragma unroll
        for (int hf = 0; hf < 2; hf++) {
            float m = mx[i][hf];
            m = fmaxf(m, __shfl_xor_sync(0xffffffffu, m, 1));
            m = fmaxf(m, __shfl_xor_sync(0xffffffffu, m, 2));
            if (tg == 0) rs[(wm * 32 + i * 16 + hf * 8 + g) * 4 + wn] = m;
        }
    __syncthreads();
    float sc[2][2], inv[2][2];
#pragma unroll
    for (int i = 0; i < 2; i++)
#pragma unroll
        for (int hf = 0; hf < 2; hf++) {
            int lr = wm * 32 + i * 16 + hf * 8 + g;
            float M = fmaxf(fmaxf(rs[lr * 4], rs[lr * 4 + 1]),
                            fmaxf(rs[lr * 4 + 2], rs[lr * 4 + 3]));
            float s = fmaxf(M, 1e-30f) * (1.f / 127.f);
            sc[i][hf] = s;
            inv[i][hf] = 1.f / s;
            if (wn == 0 && tg == 0) sOut[rowblock + lr] = s;
        }
#pragma unroll
    for (int i = 0; i < 2; i++)
#pragma unroll
        for (int j = 0; j < FJ; j++) {
            int col = wn * WN + j * 8 + tg * 2;
            size_t r0 = rowblock + wm * 32 + i * 16 + g, r1 = r0 + 8;
            int8_t a0, a1, b0, b1;
            quant2f(__int_as_float(am[i][j][0]), sc[i][0], inv[i][0], a0, b0);
            quant2f(__int_as_float(am[i][j][1]), sc[i][0], inv[i][0], a1, b1);
            *(char2*)(q1o + r0 * NT + col) = make_char2(a0, a1);
            *(char2*)(q2o + r0 * NT + col) = make_char2(b0, b1);
            quant2f(__int_as_float(am[i][j][2]), sc[i][1], inv[i][1], a0, b0);
            quant2f(__int_as_float(am[i][j][3]), sc[i][1], inv[i][1], a1, b1);
            *(char2*)(q1o + r1 * NT + col) = make_char2(a0, a1);
            *(char2*)(q2o + r1 * NT + col) = make_char2(b0, b1);
        }
}

// ---------------- flash attention (bf16 hi/lo math, fp32 out) --------------
#define AQH 0
#define AQL 10240
#define AKH 20480
#define AKL 40960
#define AVH 61440
#define AVL 78336
#define ATTN_SMEM 95232

__global__ void __launch_bounds__(256, 2)
flash_attn(const float* __restrict__ qkv, float* __restrict__ att) {
    extern __shared__ char smem[];
    const uint32_t sb = smem_u32(smem);
    const int tid = threadIdx.x, lane = tid & 31;
    const int wrow = (tid >> 5) * 16;
    const int g = lane >> 2, tg = lane & 3;
    const int qb = blockIdx.x, bh = blockIdx.y;
    const int b = bh >> 3, h = bh & 7;

    const float* qp = qkv + ((size_t)(b * T_ + qb * 128)) * C_ + h * HS_;
    const float* kp = qkv + (size_t)BT_ * C_ + (size_t)(b * T_) * C_ + h * HS_;
    const float* vp = kp + (size_t)BT_ * C_;

#pragma unroll
    for (int it = 0; it < 4; it++) {
        int i = tid + it * 256;
        int r = i >> 3, c4 = i & 7;
        float4 f = *(const float4*)(qp + (size_t)r * C_ + c4 * 4);
        f.x *= 0.0625f; f.y *= 0.0625f; f.z *= 0.0625f; f.w *= 0.0625f;
        uint32_t o = r * 80 + c4 * 8;
        uint32_t h01 = packbf2(f.x, f.y), h23 = packbf2(f.z, f.w);
        *(uint32_t*)(smem + AQH + o)     = h01;
        *(uint32_t*)(smem + AQH + o + 4) = h23;
        __nv_bfloat162* p01 = (__nv_bfloat162*)&h01;
        __nv_bfloat162* p23 = (__nv_bfloat162*)&h23;
        *(uint32_t*)(smem + AQL + o) = packbf2(f.x - __bfloat162float(p01->x),
                                               f.y - __bfloat162float(p01->y));
        *(uint32_t*)(smem + AQL + o + 4) = packbf2(f.z - __bfloat162float(p23->x),
                                                   f.w - __bfloat162float(p23->y));
    }
#pragma unroll
    for (int it = 0; it < 8; it++) {
        int i = tid + it * 256;
        int r = i >> 3, c4 = i & 7;
        float4 f = *(const float4*)(kp + (size_t)r * C_ + c4 * 4);
        uint32_t o = r * 80 + c4 * 8;
        uint32_t h01 = packbf2(f.x, f.y), h23 = packbf2(f.z, f.w);
        *(uint32_t*)(smem + AKH + o)     = h01;
        *(uint32_t*)(smem + AKH + o + 4) = h23;
        __nv_bfloat162* p01 = (__nv_bfloat162*)&h01;
        __nv_bfloat162* p23 = (__nv_bfloat162*)&h23;
        *(uint32_t*)(smem + AKL + o) = packbf2(f.x - __bfloat162float(p01->x),
                                               f.y - __bfloat162float(p01->y));
        *(uint32_t*)(smem + AKL + o + 4) = packbf2(f.z - __bfloat162float(p23->x),
                                                   f.w - __bfloat162float(p23->y));
    }
#pragma unroll
    for (int it = 0; it < 8; it++) {
        int i = tid + it * 256;
        int r = i >> 3, c4 = i & 7;
        float4 f = *(const float4*)(vp + (size_t)r * C_ + c4 * 4);
        float vals[4] = {f.x, f.y, f.z, f.w};
#pragma unroll
        for (int m = 0; m < 4; m++) {
            int d = c4 * 4 + m;
            __nv_bfloat16 hi = __float2bfloat16(vals[m]);
            *(__nv_bfloat16*)(smem + AVH + d * 528 + r * 2) = hi;
            *(__nv_bfloat16*)(smem + AVL + d * 528 + r * 2) =
                __float2bfloat16(vals[m] - __bfloat162float(hi));
        }
    }
    __syncthreads();

    uint32_t qf_h[2][4], qf_l[2][4];
#pragma unroll
    for (int ks = 0; ks < 2; ks++) {
        int r = wrow + (lane & 15);
        int hh = 2 * ks + (lane >> 4);
        ldmatrix_x4(qf_h[ks], sb + AQH + r * 80 + hh * 16);
        ldmatrix_x4(qf_l[ks], sb + AQL + r * 80 + hh * 16);
    }

    float m0 = -INFINITY, m1 = -INFINITY, l0 = 0.f, l1 = 0.f;
    float oacc[4][4];
#pragma unroll
    for (int nd = 0; nd < 4; nd++)
#pragma unroll
        for (int r = 0; r < 4; r++) oacc[nd][r] = 0.f;

    const int nch = (qb == 0) ? 2 : 4;
    const int qrow = qb * 128 + wrow + g;

    for (int ch = 0; ch < nch; ch++) {
        const int kbase = ch * 64;
        float sacc[8][4];
#pragma unroll
        for (int j = 0; j < 8; j++)
#pragma unroll
            for (int r = 0; r < 4; r++) sacc[j][r] = 0.f;
#pragma unroll
        for (int ks = 0; ks < 2; ks++) {
            uint32_t bh_[8][2], bl_[8][2];
#pragma unroll
            for (int j2 = 0; j2 < 4; j2++) {
                int r = kbase + j2 * 16 + ((lane >> 4) & 1) * 8 + (lane & 7);
                int hh = 2 * ks + ((lane >> 3) & 1);
                uint32_t t4[4];
                ldmatrix_x4(t4, sb + AKH + r * 80 + hh * 16);
                bh_[2 * j2][0] = t4[0]; bh_[2 * j2][1] = t4[1];
                bh_[2 * j2 + 1][0] = t4[2]; bh_[2 * j2 + 1][1] = t4[3];
                ldmatrix_x4(t4, sb + AKL + r * 80 + hh * 16);
                bl_[2 * j2][0] = t4[0]; bl_[2 * j2][1] = t4[1];
                bl_[2 * j2 + 1][0] = t4[2]; bl_[2 * j2 + 1][1] = t4[3];
            }
#pragma unroll
            for (int j = 0; j < 8; j++) {
                mma16816(sacc[j], qf_h[ks], bh_[j]);
                mma16816(sacc[j], qf_h[ks], bl_[j]);
                mma16816(sacc[j], qf_l[ks], bh_[j]);
            }
        }
        if (kbase + 63 > qb * 128 + wrow) {
#pragma unroll
            for (int j = 0; j < 8; j++) {
                int key = kbase + j * 8 + tg * 2;
                if (key     > qrow)     sacc[j][0] = -1e30f;
                if (key + 1 > qrow)     sacc[j][1] = -1e30f;
                if (key     > qrow + 8) sacc[j][2] = -1e30f;
                if (key + 1 > qrow + 8) sacc[j][3] = -1e30f;
            }
        }
        uint32_t ph[8][2], pl[8][2];
        {
            float mx0 = -1e30f, mx1 = -1e30f;
#pragma unroll
            for (int j = 0; j < 8; j++) {
                mx0 = fmaxf(mx0, fmaxf(sacc[j][0], sacc[j][1]));
                mx1 = fmaxf(mx1, fmaxf(sacc[j][2], sacc[j][3]));
            }
            mx0 = fmaxf(mx0, __shfl_xor_sync(0xffffffffu, mx0, 1));
            mx0 = fmaxf(mx0, __shfl_xor_sync(0xffffffffu, mx0, 2));
            mx1 = fmaxf(mx1, __shfl_xor_sync(0xffffffffu, mx1, 1));
            mx1 = fmaxf(mx1, __shfl_xor_sync(0xffffffffu, mx1, 2));
            float mn0 = fmaxf(m0, mx0), mn1 = fmaxf(m1, mx1);
            float cr0 = __expf(m0 - mn0), cr1 = __expf(m1 - mn1);
            float rs0 = 0.f, rs1 = 0.f;
#pragma unroll
            for (int j = 0; j < 8; j++) {
                float p0 = __expf(sacc[j][0] - mn0);
                float p1 = __expf(sacc[j][1] - mn0);
                float p2 = __expf(sacc[j][2] - mn1);
                float p3 = __expf(sacc[j][3] - mn1);
                rs0 += p0 + p1; rs1 += p2 + p3;
                ph[j][0] = packbf2(p0, p1);
                ph[j][1] = packbf2(p2, p3);
                __nv_bfloat162* t0 = (__nv_bfloat162*)&ph[j][0];
                __nv_bfloat162* t1 = (__nv_bfloat162*)&ph[j][1];
                pl[j][0] = packbf2(p0 - __bfloat162float(t0->x), p1 - __bfloat162float(t0->y));
                pl[j][1] = packbf2(p2 - __bfloat162float(t1->x), p3 - __bfloat162float(t1->y));
            }
            rs0 += __shfl_xor_sync(0xffffffffu, rs0, 1);
            rs0 += __shfl_xor_sync(0xffffffffu, rs0, 2);
            rs1 += __shfl_xor_sync(0xffffffffu, rs1, 1);
            rs1 += __shfl_xor_sync(0xffffffffu, rs1, 2);
            l0 = l0 * cr0 + rs0;  l1 = l1 * cr1 + rs1;
            m0 = mn0;  m1 = mn1;
#pragma unroll
            for (int nd = 0; nd < 4; nd++) {
                oacc[nd][0] *= cr0; oacc[nd][1] *= cr0;
                oacc[nd][2] *= cr1; oacc[nd][3] *= cr1;
            }
        }
#pragma unroll
        for (int kk = 0; kk < 4; kk++) {
            uint32_t pa_h[4] = {ph[2 * kk][0], ph[2 * kk][1],
                                ph[2 * kk + 1][0], ph[2 * kk + 1][1]};
            uint32_t pa_l[4] = {pl[2 * kk][0], pl[2 * kk][1],
                                pl[2 * kk + 1][0], pl[2 * kk + 1][1]};
            uint32_t vh[4][2], vl[4][2];
#pragma unroll
            for (int nd2 = 0; nd2 < 2; nd2++) {
                int r = nd2 * 16 + ((lane >> 4) & 1) * 8 + (lane & 7);
                int hh = (kbase >> 3) + 2 * kk + ((lane >> 3) & 1);
                uint32_t t4[4];
                ldmatrix_x4(t4, sb + AVH + r * 528 + hh * 16);
                vh[2 * nd2][0] = t4[0]; vh[2 * nd2][1] = t4[1];
                vh[2 * nd2 + 1][0] = t4[2]; vh[2 * nd2 + 1][1] = t4[3];
                ldmatrix_x4(t4, sb + AVL + r * 528 + hh * 16);
                vl[2 * nd2][0] = t4[0]; vl[2 * nd2][1] = t4[1];
                vl[2 * nd2 + 1][0] = t4[2]; vl[2 * nd2 + 1][1] = t4[3];
            }
#pragma unroll
            for (int nd = 0; nd < 4; nd++) {
                mma16816(oacc[nd], pa_h, vh[nd]);
                mma16816(oacc[nd], pa_h, vl[nd]);
                mma16816(oacc[nd], pa_l, vh[nd]);
            }
        }
    }

    float inv0 = 1.f / l0, inv1 = 1.f / l1;
    size_t r0 = (size_t)(b * T_) + qb * 128 + wrow + g, r1 = r0 + 8;
#pragma unroll
    for (int nd = 0; nd < 4; nd++) {
        int col = h * 32 + nd * 8 + tg * 2;
        *(float2*)(att + r0 * C_ + col) = make_float2(oacc[nd][0] * inv0, oacc[nd][1] * inv0);
        *(float2*)(att + r1 * C_ + col) = make_float2(oacc[nd][2] * inv1, oacc[nd][3] * inv1);
    }
}

// ---------------- NLL + loss ----------------
__global__ void nll_kernel(const float* __restrict__ logits, const int* __restrict__ tgt,
                           float* __restrict__ nll) {
    int warp = (blockIdx.x * blockDim.x + threadIdx.x) >> 5;
    int lane = threadIdx.x & 31;
    if (warp >= BT_) return;
    const float* l = logits + (size_t)warp * V_;
    float mx = -INFINITY;
    for (int c = lane; c < V_; c += 32) mx = fmaxf(mx, l[c]);
#pragma unroll
    for (int o = 16; o; o >>= 1) mx = fmaxf(mx, __shfl_xor_sync(0xffffffffu, mx, o));
    float s = 0.f;
    for (int c = lane; c < V_; c += 32) s += __expf(l[c] - mx);
#pragma unroll
    for (int o = 16; o; o >>= 1) s += __shfl_xor_sync(0xffffffffu, s, o);
    if (lane == 0) nll[warp] = -(l[tgt[warp]] - mx - __logf(s));
}
__global__ void reduce_loss_kernel(const float* __restrict__ nll, float* __restrict__ out) {
    __shared__ float sh[256];
    float s = 0.f;
    for (int i = threadIdx.x; i < BT_; i += 256) s += nll[i];
    sh[threadIdx.x] = s;
    __syncthreads();
    for (int st = 128; st; st >>= 1) {
        if (threadIdx.x < st) sh[threadIdx.x] += sh[threadIdx.x + st];
        __syncthreads();
    }
    if (threadIdx.x == 0) *out = sh[0] * (1.f / BT_);
}

// ---------------- host driver ----------------
extern "C" void kernel_launch(void* const* d_in, const int* in_sizes, int n_in,
                              void* d_out, int out_size) {
    const int*   idx     = (const int*)  d_in[0];
    const int*   target  = (const int*)  d_in[1];
    const float* tok_emb = (const float*)d_in[2];
    const float* pos_emb = (const float*)d_in[3];
    const float* Wq      = (const float*)d_in[4];
    const float* Wk      = (const float*)d_in[5];
    const float* Wv      = (const float*)d_in[6];
    const float* Wo      = (const float*)d_in[7];
    const float* bo      = (const float*)d_in[8];
    const float* W1      = (const float*)d_in[9];
    const float* b1      = (const float*)d_in[10];
    const float* W2      = (const float*)d_in[11];
    const float* b2_     = (const float*)d_in[12];
    const float* ln1_w   = (const float*)d_in[13];
    const float* ln1_b   = (const float*)d_in[14];
    const float* ln2_w   = (const float*)d_in[15];
    const float* ln2_b   = (const float*)d_in[16];
    const float* lnf_w   = (const float*)d_in[17];
    const float* lnf_b   = (const float*)d_in[18];
    const float* Wlm     = (const float*)d_in[19];
    const float* blm     = (const float*)d_in[20];

    float *px, *pqkv, *patt, *pnll, *psx, *psh, *psa, *psw;
    int8_t *px1, *px2, *ph1, *ph2, *pa1, *pa2, *pwi1, *pwi2;
    cudaGetSymbolAddress((void**)&px,   g_x);
    cudaGetSymbolAddress((void**)&pqkv, g_qkv);
    cudaGetSymbolAddress((void**)&patt, g_att);
    cudaGetSymbolAddress((void**)&pnll, g_nll);
    cudaGetSymbolAddress((void**)&psx,  g_sx);
    cudaGetSymbolAddress((void**)&psh,  g_sh);
    cudaGetSymbolAddress((void**)&psa,  g_sa);
    cudaGetSymbolAddress((void**)&px1,  g_x1);
    cudaGetSymbolAddress((void**)&px2,  g_x2);
    cudaGetSymbolAddress((void**)&ph1,  g_h1);
    cudaGetSymbolAddress((void**)&ph2,  g_h2);
    cudaGetSymbolAddress((void**)&pa1,  g_a1);
    cudaGetSymbolAddress((void**)&pa2,  g_a2);
    cudaGetSymbolAddress((void**)&pwi1, g_wi1);
    cudaGetSymbolAddress((void**)&pwi2, g_wi2);
    cudaGetSymbolAddress((void**)&psw,  g_sw);

    cudaFuncSetAttribute(flash_attn, cudaFuncAttributeMaxDynamicSharedMemorySize, ATTN_SMEM);
    const int smem256 = 2 * (8192 + 2 * 256 * 64);   // 81920
    const int smem128 = 2 * (8192 + 2 * 128 * 64);   // 49152
    cudaFuncSetAttribute(i8_gemm<256, 0>, cudaFuncAttributeMaxDynamicSharedMemorySize, smem256);
    cudaFuncSetAttribute(i8_gemm<256, 1>, cudaFuncAttributeMaxDynamicSharedMemorySize, smem256);
    cudaFuncSetAttribute(i8_gemm<256, 2>, cudaFuncAttributeMaxDynamicSharedMemorySize, smem256);
    cudaFuncSetAttribute(i8_gemm<128, 0>, cudaFuncAttributeMaxDynamicSharedMemorySize, smem128);

    convw_all<<<dim3(32, 37), 256>>>(Wq, Wk, Wv, Wo, W1, W2, Wlm, pwi1, pwi2, psw);
    embed_kernel<<<BT_, C_>>>(idx, tok_emb, pos_emb, px, px1, px2, psx);

    const int GM = BT_ / 64;  // 256 row blocks
#define WI(t, l) ((size_t)((t) * 6 + (l)) * WMAT)
    for (int l = 0; l < L_; l++) {
        i8_gemm<256, 0><<<dim3(GM, 3), 256, smem256>>>(px1, px2, psx,
            pwi1 + WI(0, l), pwi2 + WI(0, l), psw + (0 * 6 + l) * 256, (size_t)6 * WMAT,
            pqkv, (size_t)BT_ * C_, nullptr, nullptr, nullptr,
            nullptr, nullptr, nullptr, nullptr, C_);
        flash_attn<<<dim3(2, B_ * H_), 256, ATTN_SMEM>>>(pqkv, patt);
        quant_rows<<<BT_, C_>>>(patt, pa1, pa2, psa);
        i8_gemm<256, 2><<<GM, 256, smem256>>>(pa1, pa2, psa,
            pwi1 + WI(3, l), pwi2 + WI(3, l), psw + (3 * 6 + l) * 256, 0,
            px, 0, px1, px2, psx, bo + l * C_, px, ln1_w + l * C_, ln1_b + l * C_, C_);
        i8_gemm<256, 1><<<GM, 256, smem256>>>(px1, px2, psx,
            pwi1 + WI(4, l), pwi2 + WI(4, l), psw + (4 * 6 + l) * 256, 0,
            nullptr, 0, ph1, ph2, psh, b1 + l * C_, nullptr, nullptr, nullptr, C_);
        i8_gemm<256, 2><<<GM, 256, smem256>>>(ph1, ph2, psh,
            pwi1 + WI(5, l), pwi2 + WI(5, l), psw + (5 * 6 + l) * 256, 0,
            px, 0, px1, px2, psx, b2_ + l * C_, px, ln2_w + l * C_, ln2_b + l * C_, C_);
    }
    ln_quant<<<BT_, C_>>>(px, lnf_w, lnf_b, px1, px2, psx);

    float* logits = (out_size >= BT_ * V_) ? (float*)d_out : patt;
    i8_gemm<128, 0><<<GM, 256, smem128>>>(px1, px2, psx,
        pwi1 + (size_t)36 * WMAT, pwi2 + (size_t)36 * WMAT, psw + 36 * 256, 0,
        logits, 0, nullptr, nullptr, nullptr, blm, nullptr, nullptr, nullptr, V_);

    nll_kernel<<<(BT_ * 32 + 255) / 256, 256>>>(logits, target, pnll);

    float* loss_dst = nullptr;
    if (out_size == 1)            loss_dst = (float*)d_out;
    else if (out_size > BT_ * V_) loss_dst = (float*)d_out + BT_ * V_;
    if (loss_dst) reduce_loss_kernel<<<1, 256>>>(pnll, loss_dst);
}

// round 10
// speedup vs baseline: 2.1937x; 2.1937x over previous
#include <cuda_runtime.h>
#include <cuda_bf16.h>
#include <cstdint>
#include <math.h>

#define B_  64
#define T_  256
#define C_  256
#define H_  8
#define HS_ 32
#define L_  6
#define V_  96
#define BT_ (B_ * T_)
#define EPS_ 1e-5f

// ---------------- scratch ----------------
__device__ __align__(16) float g_x  [BT_ * C_];
__device__ __align__(16) float g_nll[BT_];

__device__ __align__(16) __nv_bfloat16 g_qvh[3 * BT_ * C_];  // QKV hi
__device__ __align__(16) __nv_bfloat16 g_qvl[3 * BT_ * C_];  // QKV lo
__device__ __align__(16) __nv_bfloat16 g_xh [BT_ * C_];
__device__ __align__(16) __nv_bfloat16 g_xl [BT_ * C_];
__device__ __align__(16) __nv_bfloat16 g_ah [BT_ * C_];
__device__ __align__(16) __nv_bfloat16 g_al [BT_ * C_];
__device__ __align__(16) __nv_bfloat16 g_hh [BT_ * C_];
__device__ __align__(16) __nv_bfloat16 g_hl [BT_ * C_];

#define WMAT_ELEMS (C_ * C_)
#define WLM_ROWS   128
#define W_TOTAL    (36 * WMAT_ELEMS + WLM_ROWS * C_)
__device__ __align__(16) __nv_bfloat16 g_wh[W_TOTAL];
__device__ __align__(16) __nv_bfloat16 g_wl[W_TOTAL];
#define WOFF(t, l) ((size_t)((t) * 6 + (l)) * WMAT_ELEMS)
#define WOFF_LM    ((size_t)36 * WMAT_ELEMS)

// ---------------- helpers ----------------
__device__ __forceinline__ uint32_t smem_u32(const void* p) {
    uint32_t a;
    asm("{ .reg .u64 t; cvta.to.shared.u64 t, %1; cvt.u32.u64 %0, t; }" : "=r"(a) : "l"(p));
    return a;
}
__device__ __forceinline__ void cp_async16(uint32_t dst, const void* src) {
    asm volatile("cp.async.cg.shared.global [%0], [%1], 16;" :: "r"(dst), "l"(src) : "memory");
}
__device__ __forceinline__ void cp_commit() { asm volatile("cp.async.commit_group;" ::: "memory"); }
template <int N>
__device__ __forceinline__ void cp_wait() {
    asm volatile("cp.async.wait_group %0;" :: "n"(N) : "memory");
}
__device__ __forceinline__ void ldmatrix_x4(uint32_t* r, uint32_t addr) {
    asm volatile("ldmatrix.sync.aligned.m8n8.x4.shared.b16 {%0,%1,%2,%3}, [%4];"
                 : "=r"(r[0]), "=r"(r[1]), "=r"(r[2]), "=r"(r[3]) : "r"(addr));
}
__device__ __forceinline__ void ldmatrix_x4t(uint32_t* r, uint32_t addr) {
    asm volatile("ldmatrix.sync.aligned.m8n8.x4.trans.shared.b16 {%0,%1,%2,%3}, [%4];"
                 : "=r"(r[0]), "=r"(r[1]), "=r"(r[2]), "=r"(r[3]) : "r"(addr));
}
__device__ __forceinline__ void mma16816(float* c, const uint32_t* a, const uint32_t* b) {
    asm volatile("mma.sync.aligned.m16n8k16.row.col.f32.bf16.bf16.f32 "
                 "{%0,%1,%2,%3}, {%4,%5,%6,%7}, {%8,%9}, {%0,%1,%2,%3};"
                 : "+f"(c[0]), "+f"(c[1]), "+f"(c[2]), "+f"(c[3])
                 : "r"(a[0]), "r"(a[1]), "r"(a[2]), "r"(a[3]), "r"(b[0]), "r"(b[1]));
}
__device__ __forceinline__ uint32_t packbf2(float a, float b) {
    __nv_bfloat162 t(__float2bfloat16(a), __float2bfloat16(b));
    return *(uint32_t*)&t;
}

// ---------------- weight transpose + hi/lo (all 37 matrices) ---------------
__global__ void convw_all(const float* __restrict__ Wq, const float* __restrict__ Wk,
                          const float* __restrict__ Wv, const float* __restrict__ Wo,
                          const float* __restrict__ W1, const float* __restrict__ W2,
                          const float* __restrict__ Wlm,
                          __nv_bfloat16* __restrict__ hi, __nv_bfloat16* __restrict__ lo) {
    const int mat = blockIdx.y;
    const int i = blockIdx.x * 256 + threadIdx.x;
    float v;
    size_t o;
    if (mat < 36) {
        if (i >= WMAT_ELEMS) return;
        const float* srcs[6] = {Wq, Wk, Wv, Wo, W1, W2};
        const float* s = srcs[mat / 6] + (size_t)(mat % 6) * WMAT_ELEMS;
        int n = i >> 8, k = i & 255;
        v = s[(size_t)k * 256 + n];
        o = (size_t)mat * WMAT_ELEMS + i;
    } else {
        if (i >= WLM_ROWS * C_) return;
        int n = i >> 8, k = i & 255;
        v = (n < V_) ? Wlm[(size_t)k * V_ + n] : 0.f;
        o = WOFF_LM + i;
    }
    __nv_bfloat16 h = __float2bfloat16(v);
    hi[o] = h;
    lo[o] = __float2bfloat16(v - __bfloat162float(h));
}

// ---------------- embedding ----------------
__global__ void embed_kernel(const int* __restrict__ idx, const float* __restrict__ tok_emb,
                             const float* __restrict__ pos_emb, float* __restrict__ x,
                             __nv_bfloat16* __restrict__ xh, __nv_bfloat16* __restrict__ xl) {
    int bt = blockIdx.x, c = threadIdx.x;
    float v = tok_emb[idx[bt] * C_ + c] + pos_emb[(bt % T_) * C_ + c];
    size_t o = (size_t)bt * C_ + c;
    x[o] = v;
    __nv_bfloat16 h = __float2bfloat16(v);
    xh[o] = h;
    xl[o] = __float2bfloat16(v - __bfloat162float(h));
}

// ---------------- HMMA GEMM (round-6 core): co-staged hi/lo, 4 stages ------
// MODE 0: fp32 out (+bias). MODE 1: bf16 hi/lo out (+bias if non-null,
//         relu iff Nout!=0; outH/outL offset by blockIdx.y*ostride).
// MODE 2: +bias +res -> LayerNorm -> fp32 + bf16 hi/lo out.
template <int NT, int MODE>
__global__ void __launch_bounds__(256)
hmma_gemm3(const __nv_bfloat16* __restrict__ Ah, const __nv_bfloat16* __restrict__ Al,
           const __nv_bfloat16* __restrict__ BhBase, const __nv_bfloat16* __restrict__ BlBase,
           size_t wstride, float* outF, size_t ostride,
           __nv_bfloat16* __restrict__ outH, __nv_bfloat16* __restrict__ outL,
           const float* __restrict__ bias, const float* __restrict__ res,
           const float* __restrict__ lnw, const float* __restrict__ lnb, int Nout) {
    extern __shared__ char smem[];
    const uint32_t sb = smem_u32(smem);
    constexpr int AHo = 0, ALo = 16384, BHo = 32768, BLo = 32768 + NT * 128;
    constexpr int STAGE = 32768 + 2 * NT * 128;
    constexpr int NCH   = 2048 + NT * 16;
    constexpr int WN  = NT / 4;
    constexpr int FJ  = WN / 8;
    constexpr int FJ2 = WN / 16;

    const int tid  = threadIdx.x;
    const int lane = tid & 31;
    const int w    = tid >> 5;
    const int wm   = w & 1;
    const int wn   = w >> 1;

    const size_t rowblock = (size_t)blockIdx.x * 128;
    const __nv_bfloat16* Bh = BhBase + blockIdx.y * wstride;
    const __nv_bfloat16* Bl = BlBase + blockIdx.y * wstride;
    if (MODE == 0) outF += blockIdx.y * ostride;
    if (MODE == 1) { outH += blockIdx.y * ostride; outL += blockIdx.y * ostride; }

    float acc[4][FJ][4];
#pragma unroll
    for (int i = 0; i < 4; i++)
#pragma unroll
        for (int j = 0; j < FJ; j++)
#pragma unroll
            for (int r = 0; r < 4; r++) acc[i][j][r] = 0.f;

    auto load_stage = [&](int s, int buf) {
        const int k0 = s * 64;
        const uint32_t base = sb + buf * STAGE;
#pragma unroll
        for (int c = tid; c < NCH; c += 256) {
            if (c < 1024) {
                int r = c >> 3, h = c & 7;
                cp_async16(base + AHo + r * 128 + 16 * (h ^ (r & 7)),
                           Ah + (rowblock + r) * 256 + k0 + h * 8);
            } else if (c < 2048) {
                int cc = c - 1024;
                int r = cc >> 3, h = cc & 7;
                cp_async16(base + ALo + r * 128 + 16 * (h ^ (r & 7)),
                           Al + (rowblock + r) * 256 + k0 + h * 8);
            } else if (c < 2048 + NT * 8) {
                int cc = c - 2048;
                int r = cc >> 3, h = cc & 7;
                cp_async16(base + BHo + r * 128 + 16 * (h ^ (r & 7)),
                           Bh + (size_t)r * 256 + k0 + h * 8);
            } else {
                int cc = c - 2048 - NT * 8;
                int r = cc >> 3, h = cc & 7;
                cp_async16(base + BLo + r * 128 + 16 * (h ^ (r & 7)),
                           Bl + (size_t)r * 256 + k0 + h * 8);
            }
        }
        cp_commit();
    };

    load_stage(0, 0);
    for (int s = 0; s < 4; s++) {
        if (s < 3) { load_stage(s + 1, (s + 1) & 1); cp_wait<1>(); }
        else       { cp_wait<0>(); }
        __syncthreads();
        const uint32_t base = sb + (s & 1) * STAGE;
#pragma unroll
        for (int ks = 0; ks < 4; ks++) {
            uint32_t ah[4][4], al[4][4];
#pragma unroll
            for (int i = 0; i < 4; i++) {
                int r = wm * 64 + i * 16 + (lane & 15);
                int hh = 2 * ks + (lane >> 4);
                uint32_t off = r * 128 + 16 * (hh ^ (r & 7));
                ldmatrix_x4(ah[i], base + AHo + off);
                ldmatrix_x4(al[i], base + ALo + off);
            }
#pragma unroll
            for (int j2 = 0; j2 < FJ2; j2++) {
                int r = wn * WN + j2 * 16 + ((lane >> 4) & 1) * 8 + (lane & 7);
                int hh = 2 * ks + ((lane >> 3) & 1);
                uint32_t off = r * 128 + 16 * (hh ^ (r & 7));
                uint32_t bh4[4], bl4[4];
                ldmatrix_x4(bh4, base + BHo + off);
                ldmatrix_x4(bl4, base + BLo + off);
#pragma unroll
                for (int i = 0; i < 4; i++) {
                    mma16816(acc[i][2 * j2],     ah[i], bh4);
                    mma16816(acc[i][2 * j2 + 1], ah[i], bh4 + 2);
                    mma16816(acc[i][2 * j2],     ah[i], bl4);
                    mma16816(acc[i][2 * j2 + 1], ah[i], bl4 + 2);
                    mma16816(acc[i][2 * j2],     al[i], bh4);
                    mma16816(acc[i][2 * j2 + 1], al[i], bh4 + 2);
                }
            }
        }
        __syncthreads();
    }

    const int g  = lane >> 2;
    const int tg = lane & 3;

    if (MODE == 0) {
#pragma unroll
        for (int i = 0; i < 4; i++)
#pragma unroll
            for (int j = 0; j < FJ; j++) {
                int col = wn * WN + j * 8 + tg * 2;
                if (col >= Nout) continue;
                size_t r0 = rowblock + wm * 64 + i * 16 + g;
                size_t r1 = r0 + 8;
                float b0 = bias ? bias[col] : 0.f;
                float b1 = bias ? bias[col + 1] : 0.f;
                *(float2*)(outF + r0 * Nout + col) =
                    make_float2(acc[i][j][0] + b0, acc[i][j][1] + b1);
                *(float2*)(outF + r1 * Nout + col) =
                    make_float2(acc[i][j][2] + b0, acc[i][j][3] + b1);
            }
    } else if (MODE == 1) {
#pragma unroll
        for (int i = 0; i < 4; i++)
#pragma unroll
            for (int j = 0; j < FJ; j++) {
                int col = wn * WN + j * 8 + tg * 2;
                size_t r0 = rowblock + wm * 64 + i * 16 + g;
                size_t r1 = r0 + 8;
                float b0 = bias ? bias[col] : 0.f;
                float b1 = bias ? bias[col + 1] : 0.f;
                float v00 = acc[i][j][0] + b0, v01 = acc[i][j][1] + b1;
                float v10 = acc[i][j][2] + b0, v11 = acc[i][j][3] + b1;
                if (Nout) {
                    v00 = fmaxf(v00, 0.f); v01 = fmaxf(v01, 0.f);
                    v10 = fmaxf(v10, 0.f); v11 = fmaxf(v11, 0.f);
                }
                __nv_bfloat16 h00 = __float2bfloat16(v00), h01 = __float2bfloat16(v01);
                __nv_bfloat16 h10 = __float2bfloat16(v10), h11 = __float2bfloat16(v11);
                *(__nv_bfloat162*)(outH + r0 * NT + col) = __nv_bfloat162(h00, h01);
                *(__nv_bfloat162*)(outH + r1 * NT + col) = __nv_bfloat162(h10, h11);
                *(__nv_bfloat162*)(outL + r0 * NT + col) = __nv_bfloat162(
                    __float2bfloat16(v00 - __bfloat162float(h00)),
                    __float2bfloat16(v01 - __bfloat162float(h01)));
                *(__nv_bfloat162*)(outL + r1 * NT + col) = __nv_bfloat162(
                    __float2bfloat16(v10 - __bfloat162float(h10)),
                    __float2bfloat16(v11 - __bfloat162float(h11)));
            }
    } else {
        float* rs = (float*)smem;
        float* rq = rs + 512;
        float vsum[4][2], vsq[4][2];
#pragma unroll
        for (int i = 0; i < 4; i++) { vsum[i][0] = vsum[i][1] = vsq[i][0] = vsq[i][1] = 0.f; }
#pragma unroll
        for (int i = 0; i < 4; i++)
#pragma unroll
            for (int j = 0; j < FJ; j++) {
                int col = wn * WN + j * 8 + tg * 2;
                size_t r0 = rowblock + wm * 64 + i * 16 + g;
                size_t r1 = r0 + 8;
                float b0 = bias[col], b1 = bias[col + 1];
                float2 q0 = *(const float2*)(res + r0 * NT + col);
                float2 q1 = *(const float2*)(res + r1 * NT + col);
                float v00 = acc[i][j][0] + b0 + q0.x;
                float v01 = acc[i][j][1] + b1 + q0.y;
                float v10 = acc[i][j][2] + b0 + q1.x;
                float v11 = acc[i][j][3] + b1 + q1.y;
                acc[i][j][0] = v00; acc[i][j][1] = v01;
                acc[i][j][2] = v10; acc[i][j][3] = v11;
                vsum[i][0] += v00 + v01;  vsq[i][0] += v00 * v00 + v01 * v01;
                vsum[i][1] += v10 + v11;  vsq[i][1] += v10 * v10 + v11 * v11;
            }
#pragma unroll
        for (int i = 0; i < 4; i++)
#pragma unroll
            for (int hf = 0; hf < 2; hf++) {
                float s = vsum[i][hf], q = vsq[i][hf];
                s += __shfl_xor_sync(0xffffffffu, s, 1);
                s += __shfl_xor_sync(0xffffffffu, s, 2);
                q += __shfl_xor_sync(0xffffffffu, q, 1);
                q += __shfl_xor_sync(0xffffffffu, q, 2);
                if (tg == 0) {
                    int lr = wm * 64 + i * 16 + hf * 8 + g;
                    rs[lr * 4 + wn] = s;
                    rq[lr * 4 + wn] = q;
                }
            }
        __syncthreads();
        float mean[4][2], rstd[4][2];
#pragma unroll
        for (int i = 0; i < 4; i++)
#pragma unroll
            for (int hf = 0; hf < 2; hf++) {
                int lr = wm * 64 + i * 16 + hf * 8 + g;
                float S = rs[lr * 4] + rs[lr * 4 + 1] + rs[lr * 4 + 2] + rs[lr * 4 + 3];
                float Q = rq[lr * 4] + rq[lr * 4 + 1] + rq[lr * 4 + 2] + rq[lr * 4 + 3];
                float mn = S * (1.f / NT);
                mean[i][hf] = mn;
                rstd[i][hf] = rsqrtf(Q * (1.f / NT) - mn * mn + EPS_);
            }
#pragma unroll
        for (int i = 0; i < 4; i++)
#pragma unroll
            for (int j = 0; j < FJ; j++) {
                int col = wn * WN + j * 8 + tg * 2;
                size_t r0 = rowblock + wm * 64 + i * 16 + g;
                size_t r1 = r0 + 8;
                float w0 = lnw[col], w1 = lnw[col + 1];
                float c0 = lnb[col], c1 = lnb[col + 1];
                float v00 = (acc[i][j][0] - mean[i][0]) * rstd[i][0] * w0 + c0;
                float v01 = (acc[i][j][1] - mean[i][0]) * rstd[i][0] * w1 + c1;
                float v10 = (acc[i][j][2] - mean[i][1]) * rstd[i][1] * w0 + c0;
                float v11 = (acc[i][j][3] - mean[i][1]) * rstd[i][1] * w1 + c1;
                *(float2*)(outF + r0 * NT + col) = make_float2(v00, v01);
                *(float2*)(outF + r1 * NT + col) = make_float2(v10, v11);
                __nv_bfloat16 h00 = __float2bfloat16(v00), h01 = __float2bfloat16(v01);
                __nv_bfloat16 h10 = __float2bfloat16(v10), h11 = __float2bfloat16(v11);
                *(__nv_bfloat162*)(outH + r0 * NT + col) = __nv_bfloat162(h00, h01);
                *(__nv_bfloat162*)(outH + r1 * NT + col) = __nv_bfloat162(h10, h11);
                *(__nv_bfloat162*)(outL + r0 * NT + col) = __nv_bfloat162(
                    __float2bfloat16(v00 - __bfloat162float(h00)),
                    __float2bfloat16(v01 - __bfloat162float(h01)));
                *(__nv_bfloat162*)(outL + r1 * NT + col) = __nv_bfloat162(
                    __float2bfloat16(v10 - __bfloat162float(h10)),
                    __float2bfloat16(v11 - __bfloat162float(h11)));
            }
    }
}

// ---------------- flash attention v2: bf16 hi/lo inputs, cp.async staging --
// smem: Q 128x(64B+16 pad) hi/lo; K 256x80 hi/lo; V 256x80 hi/lo (rows=key).
#define SQH 0
#define SQL 10240
#define SKH 20480
#define SKL 40960
#define SVH 61440
#define SVL 81920
#define ATTN_SMEM 102400

__global__ void __launch_bounds__(256, 2)
flash_attn(const __nv_bfloat16* __restrict__ qvh, const __nv_bfloat16* __restrict__ qvl,
           __nv_bfloat16* __restrict__ outH, __nv_bfloat16* __restrict__ outL) {
    extern __shared__ char smem[];
    const uint32_t sb = smem_u32(smem);
    const int tid = threadIdx.x, lane = tid & 31;
    const int wrow = (tid >> 5) * 16;
    const int g = lane >> 2, tg = lane & 3;
    const int qb = blockIdx.x, bh = blockIdx.y;
    const int b = bh >> 3, h = bh & 7;

    const size_t qtok = (size_t)(b * T_ + qb * 128);
    const size_t ktok = (size_t)(b * T_);
    // cp.async staging: 5120 16B chunks
    for (int c = tid; c < 5120; c += 256) {
        if (c < 1024) {
            int pl = c >> 9, cc = c & 511, r = cc >> 2, c4 = cc & 3;
            const __nv_bfloat16* src = (pl ? qvl : qvh) + (qtok + r) * C_ + h * HS_ + c4 * 8;
            cp_async16(sb + (pl ? SQL : SQH) + r * 80 + c4 * 16, src);
        } else if (c < 3072) {
            int cc = c - 1024, pl = cc >> 10, c2 = cc & 1023, r = c2 >> 2, c4 = c2 & 3;
            const __nv_bfloat16* src = (pl ? qvl : qvh) + (size_t)BT_ * C_ +
                                       (ktok + r) * C_ + h * HS_ + c4 * 8;
            cp_async16(sb + (pl ? SKL : SKH) + r * 80 + c4 * 16, src);
        } else {
            int cc = c - 3072, pl = cc >> 10, c2 = cc & 1023, r = c2 >> 2, c4 = c2 & 3;
            const __nv_bfloat16* src = (pl ? qvl : qvh) + 2 * (size_t)BT_ * C_ +
                                       (ktok + r) * C_ + h * HS_ + c4 * 8;
            cp_async16(sb + (pl ? SVL : SVH) + r * 80 + c4 * 16, src);
        }
    }
    cp_commit();
    cp_wait<0>();
    __syncthreads();

    uint32_t qf_h[2][4], qf_l[2][4];
#pragma unroll
    for (int ks = 0; ks < 2; ks++) {
        int r = wrow + (lane & 15);
        int hh = 2 * ks + (lane >> 4);
        ldmatrix_x4(qf_h[ks], sb + SQH + r * 80 + hh * 16);
        ldmatrix_x4(qf_l[ks], sb + SQL + r * 80 + hh * 16);
    }

    float m0 = -INFINITY, m1 = -INFINITY, l0 = 0.f, l1 = 0.f;
    float oacc[4][4];
#pragma unroll
    for (int nd = 0; nd < 4; nd++)
#pragma unroll
        for (int r = 0; r < 4; r++) oacc[nd][r] = 0.f;

    const int nch = (qb == 0) ? 2 : 4;
    const int qrow = qb * 128 + wrow + g;

    for (int ch = 0; ch < nch; ch++) {
        const int kbase = ch * 64;
        float sacc[8][4];
#pragma unroll
        for (int j = 0; j < 8; j++)
#pragma unroll
            for (int r = 0; r < 4; r++) sacc[j][r] = 0.f;
#pragma unroll
        for (int ks = 0; ks < 2; ks++) {
            uint32_t bh_[8][2], bl_[8][2];
#pragma unroll
            for (int j2 = 0; j2 < 4; j2++) {
                int r = kbase + j2 * 16 + ((lane >> 4) & 1) * 8 + (lane & 7);
                int hh = 2 * ks + ((lane >> 3) & 1);
                uint32_t t4[4];
                ldmatrix_x4(t4, sb + SKH + r * 80 + hh * 16);
                bh_[2 * j2][0] = t4[0]; bh_[2 * j2][1] = t4[1];
                bh_[2 * j2 + 1][0] = t4[2]; bh_[2 * j2 + 1][1] = t4[3];
                ldmatrix_x4(t4, sb + SKL + r * 80 + hh * 16);
                bl_[2 * j2][0] = t4[0]; bl_[2 * j2][1] = t4[1];
                bl_[2 * j2 + 1][0] = t4[2]; bl_[2 * j2 + 1][1] = t4[3];
            }
#pragma unroll
            for (int j = 0; j < 8; j++) {
                mma16816(sacc[j], qf_h[ks], bh_[j]);
                mma16816(sacc[j], qf_h[ks], bl_[j]);
                mma16816(sacc[j], qf_l[ks], bh_[j]);
            }
        }
        // scale (C^-0.5) then causal mask
#pragma unroll
        for (int j = 0; j < 8; j++)
#pragma unroll
            for (int r = 0; r < 4; r++) sacc[j][r] *= 0.0625f;
        if (kbase + 63 > qb * 128 + wrow) {
#pragma unroll
            for (int j = 0; j < 8; j++) {
                int key = kbase + j * 8 + tg * 2;
                if (key     > qrow)     sacc[j][0] = -1e30f;
                if (key + 1 > qrow)     sacc[j][1] = -1e30f;
                if (key     > qrow + 8) sacc[j][2] = -1e30f;
                if (key + 1 > qrow + 8) sacc[j][3] = -1e30f;
            }
        }
        uint32_t ph[8][2], pl[8][2];
        {
            float mx0 = -1e30f, mx1 = -1e30f;
#pragma unroll
            for (int j = 0; j < 8; j++) {
                mx0 = fmaxf(mx0, fmaxf(sacc[j][0], sacc[j][1]));
                mx1 = fmaxf(mx1, fmaxf(sacc[j][2], sacc[j][3]));
            }
            mx0 = fmaxf(mx0, __shfl_xor_sync(0xffffffffu, mx0, 1));
            mx0 = fmaxf(mx0, __shfl_xor_sync(0xffffffffu, mx0, 2));
            mx1 = fmaxf(mx1, __shfl_xor_sync(0xffffffffu, mx1, 1));
            mx1 = fmaxf(mx1, __shfl_xor_sync(0xffffffffu, mx1, 2));
            float mn0 = fmaxf(m0, mx0), mn1 = fmaxf(m1, mx1);
            float cr0 = __expf(m0 - mn0), cr1 = __expf(m1 - mn1);
            float rs0 = 0.f, rs1 = 0.f;
#pragma unroll
            for (int j = 0; j < 8; j++) {
                float p0 = __expf(sacc[j][0] - mn0);
                float p1 = __expf(sacc[j][1] - mn0);
                float p2 = __expf(sacc[j][2] - mn1);
                float p3 = __expf(sacc[j][3] - mn1);
                rs0 += p0 + p1; rs1 += p2 + p3;
                ph[j][0] = packbf2(p0, p1);
                ph[j][1] = packbf2(p2, p3);
                __nv_bfloat162* t0 = (__nv_bfloat162*)&ph[j][0];
                __nv_bfloat162* t1 = (__nv_bfloat162*)&ph[j][1];
                pl[j][0] = packbf2(p0 - __bfloat162float(t0->x), p1 - __bfloat162float(t0->y));
                pl[j][1] = packbf2(p2 - __bfloat162float(t1->x), p3 - __bfloat162float(t1->y));
            }
            rs0 += __shfl_xor_sync(0xffffffffu, rs0, 1);
            rs0 += __shfl_xor_sync(0xffffffffu, rs0, 2);
            rs1 += __shfl_xor_sync(0xffffffffu, rs1, 1);
            rs1 += __shfl_xor_sync(0xffffffffu, rs1, 2);
            l0 = l0 * cr0 + rs0;  l1 = l1 * cr1 + rs1;
            m0 = mn0;  m1 = mn1;
#pragma unroll
            for (int nd = 0; nd < 4; nd++) {
                oacc[nd][0] *= cr0; oacc[nd][1] *= cr0;
                oacc[nd][2] *= cr1; oacc[nd][3] *= cr1;
            }
        }
        // O += P V  (V^T fragments via ldmatrix.trans on [key][d] rows)
#pragma unroll
        for (int kk = 0; kk < 4; kk++) {
            uint32_t pa_h[4] = {ph[2 * kk][0], ph[2 * kk][1],
                                ph[2 * kk + 1][0], ph[2 * kk + 1][1]};
            uint32_t pa_l[4] = {pl[2 * kk][0], pl[2 * kk][1],
                                pl[2 * kk + 1][0], pl[2 * kk + 1][1]};
            uint32_t vh[4][2], vl[4][2];
#pragma unroll
            for (int nd2 = 0; nd2 < 2; nd2++) {
                int krow = kbase + 16 * kk + ((lane >> 3) & 1) * 8 + (lane & 7);
                int dcol = nd2 * 16 + (lane >> 4) * 8;
                uint32_t addr = (uint32_t)(krow * 80 + dcol * 2);
                uint32_t t4[4];
                ldmatrix_x4t(t4, sb + SVH + addr);
                vh[2 * nd2][0] = t4[0]; vh[2 * nd2][1] = t4[1];
                vh[2 * nd2 + 1][0] = t4[2]; vh[2 * nd2 + 1][1] = t4[3];
                ldmatrix_x4t(t4, sb + SVL + addr);
                vl[2 * nd2][0] = t4[0]; vl[2 * nd2][1] = t4[1];
                vl[2 * nd2 + 1][0] = t4[2]; vl[2 * nd2 + 1][1] = t4[3];
            }
#pragma unroll
            for (int nd = 0; nd < 4; nd++) {
                mma16816(oacc[nd], pa_h, vh[nd]);
                mma16816(oacc[nd], pa_h, vl[nd]);
                mma16816(oacc[nd], pa_l, vh[nd]);
            }
        }
    }

    float inv0 = 1.f / l0, inv1 = 1.f / l1;
    size_t r0 = qtok + wrow + g, r1 = r0 + 8;
#pragma unroll
    for (int nd = 0; nd < 4; nd++) {
        int col = h * 32 + nd * 8 + tg * 2;
        float v00 = oacc[nd][0] * inv0, v01 = oacc[nd][1] * inv0;
        float v10 = oacc[nd][2] * inv1, v11 = oacc[nd][3] * inv1;
        __nv_bfloat16 h00 = __float2bfloat16(v00), h01 = __float2bfloat16(v01);
        __nv_bfloat16 h10 = __float2bfloat16(v10), h11 = __float2bfloat16(v11);
        *(__nv_bfloat162*)(outH + r0 * C_ + col) = __nv_bfloat162(h00, h01);
        *(__nv_bfloat162*)(outH + r1 * C_ + col) = __nv_bfloat162(h10, h11);
        *(__nv_bfloat162*)(outL + r0 * C_ + col) = __nv_bfloat162(
            __float2bfloat16(v00 - __bfloat162float(h00)),
            __float2bfloat16(v01 - __bfloat162float(h01)));
        *(__nv_bfloat162*)(outL + r1 * C_ + col) = __nv_bfloat162(
            __float2bfloat16(v10 - __bfloat162float(h10)),
            __float2bfloat16(v11 - __bfloat162float(h11)));
    }
}

// ---------------- final layernorm ----------------
__global__ void add_ln_kernel(const float* __restrict__ x, const float* __restrict__ w,
                              const float* __restrict__ b,
                              __nv_bfloat16* __restrict__ outH, __nv_bfloat16* __restrict__ outL) {
    const int row = blockIdx.x, c = threadIdx.x;
    float v = x[(size_t)row * C_ + c];
    float s = v, s2 = v * v;
    __shared__ float sh1[8], sh2[8];
#pragma unroll
    for (int o = 16; o; o >>= 1) {
        s  += __shfl_xor_sync(0xffffffffu, s, o);
        s2 += __shfl_xor_sync(0xffffffffu, s2, o);
    }
    if ((c & 31) == 0) { sh1[c >> 5] = s; sh2[c >> 5] = s2; }
    __syncthreads();
    float S = 0.f, Q = 0.f;
#pragma unroll
    for (int i = 0; i < 8; i++) { S += sh1[i]; Q += sh2[i]; }
    float mean = S * (1.f / C_);
    float var  = Q * (1.f / C_) - mean * mean;
    float r = (v - mean) * rsqrtf(var + EPS_) * w[c] + b[c];
    size_t o = (size_t)row * C_ + c;
    __nv_bfloat16 hi = __float2bfloat16(r);
    outH[o] = hi;
    outL[o] = __float2bfloat16(r - __bfloat162float(hi));
}

// ---------------- NLL + loss ----------------
__global__ void nll_kernel(const float* __restrict__ logits, const int* __restrict__ tgt,
                           float* __restrict__ nll) {
    int warp = (blockIdx.x * blockDim.x + threadIdx.x) >> 5;
    int lane = threadIdx.x & 31;
    if (warp >= BT_) return;
    const float* l = logits + (size_t)warp * V_;
    float mx = -INFINITY;
    for (int c = lane; c < V_; c += 32) mx = fmaxf(mx, l[c]);
#pragma unroll
    for (int o = 16; o; o >>= 1) mx = fmaxf(mx, __shfl_xor_sync(0xffffffffu, mx, o));
    float s = 0.f;
    for (int c = lane; c < V_; c += 32) s += __expf(l[c] - mx);
#pragma unroll
    for (int o = 16; o; o >>= 1) s += __shfl_xor_sync(0xffffffffu, s, o);
    if (lane == 0) nll[warp] = -(l[tgt[warp]] - mx - __logf(s));
}
__global__ void reduce_loss_kernel(const float* __restrict__ nll, float* __restrict__ out) {
    __shared__ float sh[256];
    float s = 0.f;
    for (int i = threadIdx.x; i < BT_; i += 256) s += nll[i];
    sh[threadIdx.x] = s;
    __syncthreads();
    for (int st = 128; st; st >>= 1) {
        if (threadIdx.x < st) sh[threadIdx.x] += sh[threadIdx.x + st];
        __syncthreads();
    }
    if (threadIdx.x == 0) *out = sh[0] * (1.f / BT_);
}

// ---------------- host driver ----------------
extern "C" void kernel_launch(void* const* d_in, const int* in_sizes, int n_in,
                              void* d_out, int out_size) {
    const int*   idx     = (const int*)  d_in[0];
    const int*   target  = (const int*)  d_in[1];
    const float* tok_emb = (const float*)d_in[2];
    const float* pos_emb = (const float*)d_in[3];
    const float* Wq      = (const float*)d_in[4];
    const float* Wk      = (const float*)d_in[5];
    const float* Wv      = (const float*)d_in[6];
    const float* Wo      = (const float*)d_in[7];
    const float* bo      = (const float*)d_in[8];
    const float* W1      = (const float*)d_in[9];
    const float* b1      = (const float*)d_in[10];
    const float* W2      = (const float*)d_in[11];
    const float* b2_     = (const float*)d_in[12];
    const float* ln1_w   = (const float*)d_in[13];
    const float* ln1_b   = (const float*)d_in[14];
    const float* ln2_w   = (const float*)d_in[15];
    const float* ln2_b   = (const float*)d_in[16];
    const float* lnf_w   = (const float*)d_in[17];
    const float* lnf_b   = (const float*)d_in[18];
    const float* Wlm     = (const float*)d_in[19];
    const float* blm     = (const float*)d_in[20];

    float *px, *pnll;
    __nv_bfloat16 *pqvh, *pqvl, *pxh, *pxl, *pah, *pal, *phh, *phl, *pwh, *pwl;
    cudaGetSymbolAddress((void**)&px,   g_x);
    cudaGetSymbolAddress((void**)&pnll, g_nll);
    cudaGetSymbolAddress((void**)&pqvh, g_qvh);
    cudaGetSymbolAddress((void**)&pqvl, g_qvl);
    cudaGetSymbolAddress((void**)&pxh,  g_xh);
    cudaGetSymbolAddress((void**)&pxl,  g_xl);
    cudaGetSymbolAddress((void**)&pah,  g_ah);
    cudaGetSymbolAddress((void**)&pal,  g_al);
    cudaGetSymbolAddress((void**)&phh,  g_hh);
    cudaGetSymbolAddress((void**)&phl,  g_hl);
    cudaGetSymbolAddress((void**)&pwh,  g_wh);
    cudaGetSymbolAddress((void**)&pwl,  g_wl);

    cudaFuncSetAttribute(flash_attn, cudaFuncAttributeMaxDynamicSharedMemorySize, ATTN_SMEM);
    const int smem256 = 2 * (32768 + 2 * 256 * 128);
    const int smem128 = 2 * (32768 + 2 * 128 * 128);
    cudaFuncSetAttribute(hmma_gemm3<256, 0>, cudaFuncAttributeMaxDynamicSharedMemorySize, smem256);
    cudaFuncSetAttribute(hmma_gemm3<256, 1>, cudaFuncAttributeMaxDynamicSharedMemorySize, smem256);
    cudaFuncSetAttribute(hmma_gemm3<256, 2>, cudaFuncAttributeMaxDynamicSharedMemorySize, smem256);
    cudaFuncSetAttribute(hmma_gemm3<128, 0>, cudaFuncAttributeMaxDynamicSharedMemorySize, smem128);

    convw_all<<<dim3(256, 37), 256>>>(Wq, Wk, Wv, Wo, W1, W2, Wlm, pwh, pwl);
    embed_kernel<<<BT_, C_>>>(idx, tok_emb, pos_emb, px, pxh, pxl);

    const size_t QKV_OSTRIDE = (size_t)BT_ * C_;
    const size_t QKV_WSTRIDE = (size_t)6 * WMAT_ELEMS;

    for (int l = 0; l < L_; l++) {
        // QKV -> bf16 hi/lo (MODE 1, no bias, no relu)
        hmma_gemm3<256, 1><<<dim3(128, 3), 256, smem256>>>(pxh, pxl,
            pwh + WOFF(0, l), pwl + WOFF(0, l), QKV_WSTRIDE,
            nullptr, QKV_OSTRIDE, pqvh, pqvl, nullptr, nullptr, nullptr, nullptr, 0);
        flash_attn<<<dim3(2, B_ * H_), 256, ATTN_SMEM>>>(pqvh, pqvl, pah, pal);
        hmma_gemm3<256, 2><<<dim3(128, 1), 256, smem256>>>(pah, pal,
            pwh + WOFF(3, l), pwl + WOFF(3, l), 0,
            px, 0, pxh, pxl, bo + l * C_, px, ln1_w + l * C_, ln1_b + l * C_, C_);
        hmma_gemm3<256, 1><<<dim3(128, 1), 256, smem256>>>(pxh, pxl,
            pwh + WOFF(4, l), pwl + WOFF(4, l), 0,
            nullptr, 0, phh, phl, b1 + l * C_, nullptr, nullptr, nullptr, 1);
        hmma_gemm3<256, 2><<<dim3(128, 1), 256, smem256>>>(phh, phl,
            pwh + WOFF(5, l), pwl + WOFF(5, l), 0,
            px, 0, pxh, pxl, b2_ + l * C_, px, ln2_w + l * C_, ln2_b + l * C_, C_);
    }
    add_ln_kernel<<<BT_, C_>>>(px, lnf_w, lnf_b, pxh, pxl);

    float* logits = (out_size >= BT_ * V_) ? (float*)d_out : px;
    hmma_gemm3<128, 0><<<dim3(128, 1), 256, smem128>>>(pxh, pxl,
        pwh + WOFF_LM, pwl + WOFF_LM, 0,
        logits, 0, nullptr, nullptr, blm, nullptr, nullptr, nullptr, V_);

    nll_kernel<<<(BT_ * 32 + 255) / 256, 256>>>(logits, target, pnll);

    float* loss_dst = nullptr;
    if (out_size == 1)            loss_dst = (float*)d_out;
    else if (out_size > BT_ * V_) loss_dst = (float*)d_out + BT_ * V_;
    if (loss_dst) reduce_loss_kernel<<<1, 256>>>(pnll, loss_dst);
}

// round 11
// speedup vs baseline: 2.3247x; 1.0597x over previous
#include <cuda_runtime.h>
#include <cuda_bf16.h>
#include <cstdint>
#include <math.h>

#define B_  64
#define T_  256
#define C_  256
#define H_  8
#define HS_ 32
#define L_  6
#define V_  96
#define BT_ (B_ * T_)
#define EPS_ 1e-5f

// ---------------- scratch ----------------
__device__ __align__(16) float g_x  [BT_ * C_];
__device__ __align__(16) float g_qkv[3 * BT_ * C_];
__device__ __align__(16) float g_nll[BT_];

__device__ __align__(16) __nv_bfloat16 g_xh [BT_ * C_];
__device__ __align__(16) __nv_bfloat16 g_xl [BT_ * C_];
__device__ __align__(16) __nv_bfloat16 g_ah [BT_ * C_];
__device__ __align__(16) __nv_bfloat16 g_al [BT_ * C_];
__device__ __align__(16) __nv_bfloat16 g_hh [BT_ * C_];
__device__ __align__(16) __nv_bfloat16 g_hl [BT_ * C_];

#define WMAT_ELEMS (C_ * C_)
#define WLM_ROWS   128
#define W_TOTAL    (36 * WMAT_ELEMS + WLM_ROWS * C_)
__device__ __align__(16) __nv_bfloat16 g_wh[W_TOTAL];
__device__ __align__(16) __nv_bfloat16 g_wl[W_TOTAL];
#define WOFF(t, l) ((size_t)((t) * 6 + (l)) * WMAT_ELEMS)
#define WOFF_LM    ((size_t)36 * WMAT_ELEMS)

// ---------------- helpers ----------------
__device__ __forceinline__ uint32_t smem_u32(const void* p) {
    uint32_t a;
    asm("{ .reg .u64 t; cvta.to.shared.u64 t, %1; cvt.u32.u64 %0, t; }" : "=r"(a) : "l"(p));
    return a;
}
__device__ __forceinline__ void cp_async16(uint32_t dst, const void* src) {
    asm volatile("cp.async.cg.shared.global [%0], [%1], 16;" :: "r"(dst), "l"(src) : "memory");
}
__device__ __forceinline__ void cp_commit() { asm volatile("cp.async.commit_group;" ::: "memory"); }
template <int N>
__device__ __forceinline__ void cp_wait() {
    asm volatile("cp.async.wait_group %0;" :: "n"(N) : "memory");
}
__device__ __forceinline__ void ldmatrix_x4(uint32_t* r, uint32_t addr) {
    asm volatile("ldmatrix.sync.aligned.m8n8.x4.shared.b16 {%0,%1,%2,%3}, [%4];"
                 : "=r"(r[0]), "=r"(r[1]), "=r"(r[2]), "=r"(r[3]) : "r"(addr));
}
__device__ __forceinline__ void mma16816(float* c, const uint32_t* a, const uint32_t* b) {
    asm volatile("mma.sync.aligned.m16n8k16.row.col.f32.bf16.bf16.f32 "
                 "{%0,%1,%2,%3}, {%4,%5,%6,%7}, {%8,%9}, {%0,%1,%2,%3};"
                 : "+f"(c[0]), "+f"(c[1]), "+f"(c[2]), "+f"(c[3])
                 : "r"(a[0]), "r"(a[1]), "r"(a[2]), "r"(a[3]), "r"(b[0]), "r"(b[1]));
}
__device__ __forceinline__ uint32_t packbf2(float a, float b) {
    __nv_bfloat162 t(__float2bfloat16(a), __float2bfloat16(b));
    return *(uint32_t*)&t;
}

// ---------------- weight transpose + hi/lo ----------------
__global__ void convw_all(const float* __restrict__ Wq, const float* __restrict__ Wk,
                          const float* __restrict__ Wv, const float* __restrict__ Wo,
                          const float* __restrict__ W1, const float* __restrict__ W2,
                          const float* __restrict__ Wlm,
                          __nv_bfloat16* __restrict__ hi, __nv_bfloat16* __restrict__ lo) {
    const int mat = blockIdx.y;
    const int i = blockIdx.x * 256 + threadIdx.x;
    float v;
    size_t o;
    if (mat < 36) {
        if (i >= WMAT_ELEMS) return;
        const float* srcs[6] = {Wq, Wk, Wv, Wo, W1, W2};
        const float* s = srcs[mat / 6] + (size_t)(mat % 6) * WMAT_ELEMS;
        int n = i >> 8, k = i & 255;
        v = s[(size_t)k * 256 + n];
        o = (size_t)mat * WMAT_ELEMS + i;
    } else {
        if (i >= WLM_ROWS * C_) return;
        int n = i >> 8, k = i & 255;
        v = (n < V_) ? Wlm[(size_t)k * V_ + n] : 0.f;
        o = WOFF_LM + i;
    }
    __nv_bfloat16 h = __float2bfloat16(v);
    hi[o] = h;
    lo[o] = __float2bfloat16(v - __bfloat162float(h));
}

// ---------------- embedding ----------------
__global__ void embed_kernel(const int* __restrict__ idx, const float* __restrict__ tok_emb,
                             const float* __restrict__ pos_emb, float* __restrict__ x,
                             __nv_bfloat16* __restrict__ xh, __nv_bfloat16* __restrict__ xl) {
    int bt = blockIdx.x, c = threadIdx.x;
    float v = tok_emb[idx[bt] * C_ + c] + pos_emb[(bt % T_) * C_ + c];
    size_t o = (size_t)bt * C_ + c;
    x[o] = v;
    __nv_bfloat16 h = __float2bfloat16(v);
    xh[o] = h;
    xl[o] = __float2bfloat16(v - __bfloat162float(h));
}

// ---------------- HMMA GEMM (round-6 core, term-major MMA order) -----------
template <int NT, int MODE>
__global__ void __launch_bounds__(256)
hmma_gemm3(const __nv_bfloat16* __restrict__ Ah, const __nv_bfloat16* __restrict__ Al,
           const __nv_bfloat16* __restrict__ BhBase, const __nv_bfloat16* __restrict__ BlBase,
           size_t wstride, float* outF, size_t ostride,
           __nv_bfloat16* __restrict__ outH, __nv_bfloat16* __restrict__ outL,
           const float* __restrict__ bias, const float* __restrict__ res,
           const float* __restrict__ lnw, const float* __restrict__ lnb, int Nout) {
    extern __shared__ char smem[];
    const uint32_t sb = smem_u32(smem);
    constexpr int AHo = 0, ALo = 16384, BHo = 32768, BLo = 32768 + NT * 128;
    constexpr int STAGE = 32768 + 2 * NT * 128;
    constexpr int NCH   = 2048 + NT * 16;
    constexpr int WN  = NT / 4;
    constexpr int FJ  = WN / 8;
    constexpr int FJ2 = WN / 16;

    const int tid  = threadIdx.x;
    const int lane = tid & 31;
    const int w    = tid >> 5;
    const int wm   = w & 1;
    const int wn   = w >> 1;

    const size_t rowblock = (size_t)blockIdx.x * 128;
    const __nv_bfloat16* Bh = BhBase + blockIdx.y * wstride;
    const __nv_bfloat16* Bl = BlBase + blockIdx.y * wstride;
    if (MODE == 0) outF += blockIdx.y * ostride;

    float acc[4][FJ][4];
#pragma unroll
    for (int i = 0; i < 4; i++)
#pragma unroll
        for (int j = 0; j < FJ; j++)
#pragma unroll
            for (int r = 0; r < 4; r++) acc[i][j][r] = 0.f;

    auto load_stage = [&](int s, int buf) {
        const int k0 = s * 64;
        const uint32_t base = sb + buf * STAGE;
#pragma unroll
        for (int c = tid; c < NCH; c += 256) {
            if (c < 1024) {
                int r = c >> 3, h = c & 7;
                cp_async16(base + AHo + r * 128 + 16 * (h ^ (r & 7)),
                           Ah + (rowblock + r) * 256 + k0 + h * 8);
            } else if (c < 2048) {
                int cc = c - 1024;
                int r = cc >> 3, h = cc & 7;
                cp_async16(base + ALo + r * 128 + 16 * (h ^ (r & 7)),
                           Al + (rowblock + r) * 256 + k0 + h * 8);
            } else if (c < 2048 + NT * 8) {
                int cc = c - 2048;
                int r = cc >> 3, h = cc & 7;
                cp_async16(base + BHo + r * 128 + 16 * (h ^ (r & 7)),
                           Bh + (size_t)r * 256 + k0 + h * 8);
            } else {
                int cc = c - 2048 - NT * 8;
                int r = cc >> 3, h = cc & 7;
                cp_async16(base + BLo + r * 128 + 16 * (h ^ (r & 7)),
                           Bl + (size_t)r * 256 + k0 + h * 8);
            }
        }
        cp_commit();
    };

    load_stage(0, 0);
    for (int s = 0; s < 4; s++) {
        if (s < 3) { load_stage(s + 1, (s + 1) & 1); cp_wait<1>(); }
        else       { cp_wait<0>(); }
        __syncthreads();
        const uint32_t base = sb + (s & 1) * STAGE;
#pragma unroll
        for (int ks = 0; ks < 4; ks++) {
            uint32_t ah[4][4], al[4][4];
#pragma unroll
            for (int i = 0; i < 4; i++) {
                int r = wm * 64 + i * 16 + (lane & 15);
                int hh = 2 * ks + (lane >> 4);
                uint32_t off = r * 128 + 16 * (hh ^ (r & 7));
                ldmatrix_x4(ah[i], base + AHo + off);
                ldmatrix_x4(al[i], base + ALo + off);
            }
#pragma unroll
            for (int j2 = 0; j2 < FJ2; j2++) {
                int r = wn * WN + j2 * 16 + ((lane >> 4) & 1) * 8 + (lane & 7);
                int hh = 2 * ks + ((lane >> 3) & 1);
                uint32_t off = r * 128 + 16 * (hh ^ (r & 7));
                uint32_t bh4[4], bl4[4];
                ldmatrix_x4(bh4, base + BHo + off);
                ldmatrix_x4(bl4, base + BLo + off);
                // term-major: same-accumulator reuse distance = 8 MMAs
#pragma unroll
                for (int i = 0; i < 4; i++) {
                    mma16816(acc[i][2 * j2],     ah[i], bh4);
                    mma16816(acc[i][2 * j2 + 1], ah[i], bh4 + 2);
                }
#pragma unroll
                for (int i = 0; i < 4; i++) {
                    mma16816(acc[i][2 * j2],     ah[i], bl4);
                    mma16816(acc[i][2 * j2 + 1], ah[i], bl4 + 2);
                }
#pragma unroll
                for (int i = 0; i < 4; i++) {
                    mma16816(acc[i][2 * j2],     al[i], bh4);
                    mma16816(acc[i][2 * j2 + 1], al[i], bh4 + 2);
                }
            }
        }
        __syncthreads();
    }

    const int g  = lane >> 2;
    const int tg = lane & 3;

    if (MODE == 0) {
#pragma unroll
        for (int i = 0; i < 4; i++)
#pragma unroll
            for (int j = 0; j < FJ; j++) {
                int col = wn * WN + j * 8 + tg * 2;
                if (col >= Nout) continue;
                size_t r0 = rowblock + wm * 64 + i * 16 + g;
                size_t r1 = r0 + 8;
                float b0 = bias ? bias[col] : 0.f;
                float b1 = bias ? bias[col + 1] : 0.f;
                *(float2*)(outF + r0 * Nout + col) =
                    make_float2(acc[i][j][0] + b0, acc[i][j][1] + b1);
                *(float2*)(outF + r1 * Nout + col) =
                    make_float2(acc[i][j][2] + b0, acc[i][j][3] + b1);
            }
    } else if (MODE == 1) {
#pragma unroll
        for (int i = 0; i < 4; i++)
#pragma unroll
            for (int j = 0; j < FJ; j++) {
                int col = wn * WN + j * 8 + tg * 2;
                size_t r0 = rowblock + wm * 64 + i * 16 + g;
                size_t r1 = r0 + 8;
                float b0 = bias[col], b1 = bias[col + 1];
                float v00 = fmaxf(acc[i][j][0] + b0, 0.f);
                float v01 = fmaxf(acc[i][j][1] + b1, 0.f);
                float v10 = fmaxf(acc[i][j][2] + b0, 0.f);
                float v11 = fmaxf(acc[i][j][3] + b1, 0.f);
                __nv_bfloat16 h00 = __float2bfloat16(v00), h01 = __float2bfloat16(v01);
                __nv_bfloat16 h10 = __float2bfloat16(v10), h11 = __float2bfloat16(v11);
                *(__nv_bfloat162*)(outH + r0 * NT + col) = __nv_bfloat162(h00, h01);
                *(__nv_bfloat162*)(outH + r1 * NT + col) = __nv_bfloat162(h10, h11);
                *(__nv_bfloat162*)(outL + r0 * NT + col) = __nv_bfloat162(
                    __float2bfloat16(v00 - __bfloat162float(h00)),
                    __float2bfloat16(v01 - __bfloat162float(h01)));
                *(__nv_bfloat162*)(outL + r1 * NT + col) = __nv_bfloat162(
                    __float2bfloat16(v10 - __bfloat162float(h10)),
                    __float2bfloat16(v11 - __bfloat162float(h11)));
            }
    } else {
        float* rs = (float*)smem;
        float* rq = rs + 512;
        float vsum[4][2], vsq[4][2];
#pragma unroll
        for (int i = 0; i < 4; i++) { vsum[i][0] = vsum[i][1] = vsq[i][0] = vsq[i][1] = 0.f; }
#pragma unroll
        for (int i = 0; i < 4; i++)
#pragma unroll
            for (int j = 0; j < FJ; j++) {
                int col = wn * WN + j * 8 + tg * 2;
                size_t r0 = rowblock + wm * 64 + i * 16 + g;
                size_t r1 = r0 + 8;
                float b0 = bias[col], b1 = bias[col + 1];
                float2 q0 = *(const float2*)(res + r0 * NT + col);
                float2 q1 = *(const float2*)(res + r1 * NT + col);
                float v00 = acc[i][j][0] + b0 + q0.x;
                float v01 = acc[i][j][1] + b1 + q0.y;
                float v10 = acc[i][j][2] + b0 + q1.x;
                float v11 = acc[i][j][3] + b1 + q1.y;
                acc[i][j][0] = v00; acc[i][j][1] = v01;
                acc[i][j][2] = v10; acc[i][j][3] = v11;
                vsum[i][0] += v00 + v01;  vsq[i][0] += v00 * v00 + v01 * v01;
                vsum[i][1] += v10 + v11;  vsq[i][1] += v10 * v10 + v11 * v11;
            }
#pragma unroll
        for (int i = 0; i < 4; i++)
#pragma unroll
            for (int hf = 0; hf < 2; hf++) {
                float s = vsum[i][hf], q = vsq[i][hf];
                s += __shfl_xor_sync(0xffffffffu, s, 1);
                s += __shfl_xor_sync(0xffffffffu, s, 2);
                q += __shfl_xor_sync(0xffffffffu, q, 1);
                q += __shfl_xor_sync(0xffffffffu, q, 2);
                if (tg == 0) {
                    int lr = wm * 64 + i * 16 + hf * 8 + g;
                    rs[lr * 4 + wn] = s;
                    rq[lr * 4 + wn] = q;
                }
            }
        __syncthreads();
        float mean[4][2], rstd[4][2];
#pragma unroll
        for (int i = 0; i < 4; i++)
#pragma unroll
            for (int hf = 0; hf < 2; hf++) {
                int lr = wm * 64 + i * 16 + hf * 8 + g;
                float S = rs[lr * 4] + rs[lr * 4 + 1] + rs[lr * 4 + 2] + rs[lr * 4 + 3];
                float Q = rq[lr * 4] + rq[lr * 4 + 1] + rq[lr * 4 + 2] + rq[lr * 4 + 3];
                float mn = S * (1.f / NT);
                mean[i][hf] = mn;
                rstd[i][hf] = rsqrtf(Q * (1.f / NT) - mn * mn + EPS_);
            }
#pragma unroll
        for (int i = 0; i < 4; i++)
#pragma unroll
            for (int j = 0; j < FJ; j++) {
                int col = wn * WN + j * 8 + tg * 2;
                size_t r0 = rowblock + wm * 64 + i * 16 + g;
                size_t r1 = r0 + 8;
                float w0 = lnw[col], w1 = lnw[col + 1];
                float c0 = lnb[col], c1 = lnb[col + 1];
                float v00 = (acc[i][j][0] - mean[i][0]) * rstd[i][0] * w0 + c0;
                float v01 = (acc[i][j][1] - mean[i][0]) * rstd[i][0] * w1 + c1;
                float v10 = (acc[i][j][2] - mean[i][1]) * rstd[i][1] * w0 + c0;
                float v11 = (acc[i][j][3] - mean[i][1]) * rstd[i][1] * w1 + c1;
                *(float2*)(outF + r0 * NT + col) = make_float2(v00, v01);
                *(float2*)(outF + r1 * NT + col) = make_float2(v10, v11);
                __nv_bfloat16 h00 = __float2bfloat16(v00), h01 = __float2bfloat16(v01);
                __nv_bfloat16 h10 = __float2bfloat16(v10), h11 = __float2bfloat16(v11);
                *(__nv_bfloat162*)(outH + r0 * NT + col) = __nv_bfloat162(h00, h01);
                *(__nv_bfloat162*)(outH + r1 * NT + col) = __nv_bfloat162(h10, h11);
                *(__nv_bfloat162*)(outL + r0 * NT + col) = __nv_bfloat162(
                    __float2bfloat16(v00 - __bfloat162float(h00)),
                    __float2bfloat16(v01 - __bfloat162float(h01)));
                *(__nv_bfloat162*)(outL + r1 * NT + col) = __nv_bfloat162(
                    __float2bfloat16(v10 - __bfloat162float(h10)),
                    __float2bfloat16(v11 - __bfloat162float(h11)));
            }
    }
}

// ---------------- flash attention (round-6, term-major MMA order) ----------
#define AQH 0
#define AQL 10240
#define AKH 20480
#define AKL 40960
#define AVH 61440
#define AVL 78336
#define ATTN_SMEM 95232

__global__ void __launch_bounds__(256, 2)
flash_attn(const float* __restrict__ qkv,
           __nv_bfloat16* __restrict__ outH, __nv_bfloat16* __restrict__ outL) {
    extern __shared__ char smem[];
    const uint32_t sb = smem_u32(smem);
    const int tid = threadIdx.x, lane = tid & 31;
    const int wrow = (tid >> 5) * 16;
    const int g = lane >> 2, tg = lane & 3;
    const int qb = blockIdx.x, bh = blockIdx.y;
    const int b = bh >> 3, h = bh & 7;

    const float* qp = qkv + ((size_t)(b * T_ + qb * 128)) * C_ + h * HS_;
    const float* kp = qkv + (size_t)BT_ * C_ + (size_t)(b * T_) * C_ + h * HS_;
    const float* vp = kp + (size_t)BT_ * C_;

#pragma unroll
    for (int it = 0; it < 4; it++) {
        int i = tid + it * 256;
        int r = i >> 3, c4 = i & 7;
        float4 f = *(const float4*)(qp + (size_t)r * C_ + c4 * 4);
        f.x *= 0.0625f; f.y *= 0.0625f; f.z *= 0.0625f; f.w *= 0.0625f;
        uint32_t o = r * 80 + c4 * 8;
        uint32_t h01 = packbf2(f.x, f.y), h23 = packbf2(f.z, f.w);
        *(uint32_t*)(smem + AQH + o)     = h01;
        *(uint32_t*)(smem + AQH + o + 4) = h23;
        __nv_bfloat162* p01 = (__nv_bfloat162*)&h01;
        __nv_bfloat162* p23 = (__nv_bfloat162*)&h23;
        *(uint32_t*)(smem + AQL + o) = packbf2(f.x - __bfloat162float(p01->x),
                                               f.y - __bfloat162float(p01->y));
        *(uint32_t*)(smem + AQL + o + 4) = packbf2(f.z - __bfloat162float(p23->x),
                                                   f.w - __bfloat162float(p23->y));
    }
#pragma unroll
    for (int it = 0; it < 8; it++) {
        int i = tid + it * 256;
        int r = i >> 3, c4 = i & 7;
        float4 f = *(const float4*)(kp + (size_t)r * C_ + c4 * 4);
        uint32_t o = r * 80 + c4 * 8;
        uint32_t h01 = packbf2(f.x, f.y), h23 = packbf2(f.z, f.w);
        *(uint32_t*)(smem + AKH + o)     = h01;
        *(uint32_t*)(smem + AKH + o + 4) = h23;
        __nv_bfloat162* p01 = (__nv_bfloat162*)&h01;
        __nv_bfloat162* p23 = (__nv_bfloat162*)&h23;
        *(uint32_t*)(smem + AKL + o) = packbf2(f.x - __bfloat162float(p01->x),
                                               f.y - __bfloat162float(p01->y));
        *(uint32_t*)(smem + AKL + o + 4) = packbf2(f.z - __bfloat162float(p23->x),
                                                   f.w - __bfloat162float(p23->y));
    }
#pragma unroll
    for (int it = 0; it < 8; it++) {
        int i = tid + it * 256;
        int r = i >> 3, c4 = i & 7;
        float4 f = *(const float4*)(vp + (size_t)r * C_ + c4 * 4);
        float vals[4] = {f.x, f.y, f.z, f.w};
#pragma unroll
        for (int m = 0; m < 4; m++) {
            int d = c4 * 4 + m;
            __nv_bfloat16 hi = __float2bfloat16(vals[m]);
            *(__nv_bfloat16*)(smem + AVH + d * 528 + r * 2) = hi;
            *(__nv_bfloat16*)(smem + AVL + d * 528 + r * 2) =
                __float2bfloat16(vals[m] - __bfloat162float(hi));
        }
    }
    __syncthreads();

    uint32_t qf_h[2][4], qf_l[2][4];
#pragma unroll
    for (int ks = 0; ks < 2; ks++) {
        int r = wrow + (lane & 15);
        int hh = 2 * ks + (lane >> 4);
        ldmatrix_x4(qf_h[ks], sb + AQH + r * 80 + hh * 16);
        ldmatrix_x4(qf_l[ks], sb + AQL + r * 80 + hh * 16);
    }

    float m0 = -INFINITY, m1 = -INFINITY, l0 = 0.f, l1 = 0.f;
    float oacc[4][4];
#pragma unroll
    for (int nd = 0; nd < 4; nd++)
#pragma unroll
        for (int r = 0; r < 4; r++) oacc[nd][r] = 0.f;

    const int nch = (qb == 0) ? 2 : 4;
    const int qrow = qb * 128 + wrow + g;

    for (int ch = 0; ch < nch; ch++) {
        const int kbase = ch * 64;
        float sacc[8][4];
#pragma unroll
        for (int j = 0; j < 8; j++)
#pragma unroll
            for (int r = 0; r < 4; r++) sacc[j][r] = 0.f;
#pragma unroll
        for (int ks = 0; ks < 2; ks++) {
            uint32_t bh_[8][2], bl_[8][2];
#pragma unroll
            for (int j2 = 0; j2 < 4; j2++) {
                int r = kbase + j2 * 16 + ((lane >> 4) & 1) * 8 + (lane & 7);
                int hh = 2 * ks + ((lane >> 3) & 1);
                uint32_t t4[4];
                ldmatrix_x4(t4, sb + AKH + r * 80 + hh * 16);
                bh_[2 * j2][0] = t4[0]; bh_[2 * j2][1] = t4[1];
                bh_[2 * j2 + 1][0] = t4[2]; bh_[2 * j2 + 1][1] = t4[3];
                ldmatrix_x4(t4, sb + AKL + r * 80 + hh * 16);
                bl_[2 * j2][0] = t4[0]; bl_[2 * j2][1] = t4[1];
                bl_[2 * j2 + 1][0] = t4[2]; bl_[2 * j2 + 1][1] = t4[3];
            }
            // term-major: same-acc gap = 8
#pragma unroll
            for (int j = 0; j < 8; j++) mma16816(sacc[j], qf_h[ks], bh_[j]);
#pragma unroll
            for (int j = 0; j < 8; j++) mma16816(sacc[j], qf_h[ks], bl_[j]);
#pragma unroll
            for (int j = 0; j < 8; j++) mma16816(sacc[j], qf_l[ks], bh_[j]);
        }
        if (kbase + 63 > qb * 128 + wrow) {
#pragma unroll
            for (int j = 0; j < 8; j++) {
                int key = kbase + j * 8 + tg * 2;
                if (key     > qrow)     sacc[j][0] = -1e30f;
                if (key + 1 > qrow)     sacc[j][1] = -1e30f;
                if (key     > qrow + 8) sacc[j][2] = -1e30f;
                if (key + 1 > qrow + 8) sacc[j][3] = -1e30f;
            }
        }
        uint32_t ph[8][2], pl[8][2];
        {
            float mx0 = -1e30f, mx1 = -1e30f;
#pragma unroll
            for (int j = 0; j < 8; j++) {
                mx0 = fmaxf(mx0, fmaxf(sacc[j][0], sacc[j][1]));
                mx1 = fmaxf(mx1, fmaxf(sacc[j][2], sacc[j][3]));
            }
            mx0 = fmaxf(mx0, __shfl_xor_sync(0xffffffffu, mx0, 1));
            mx0 = fmaxf(mx0, __shfl_xor_sync(0xffffffffu, mx0, 2));
            mx1 = fmaxf(mx1, __shfl_xor_sync(0xffffffffu, mx1, 1));
            mx1 = fmaxf(mx1, __shfl_xor_sync(0xffffffffu, mx1, 2));
            float mn0 = fmaxf(m0, mx0), mn1 = fmaxf(m1, mx1);
            float cr0 = __expf(m0 - mn0), cr1 = __expf(m1 - mn1);
            float rs0 = 0.f, rs1 = 0.f;
#pragma unroll
            for (int j = 0; j < 8; j++) {
                float p0 = __expf(sacc[j][0] - mn0);
                float p1 = __expf(sacc[j][1] - mn0);
                float p2 = __expf(sacc[j][2] - mn1);
                float p3 = __expf(sacc[j][3] - mn1);
                rs0 += p0 + p1; rs1 += p2 + p3;
                ph[j][0] = packbf2(p0, p1);
                ph[j][1] = packbf2(p2, p3);
                __nv_bfloat162* t0 = (__nv_bfloat162*)&ph[j][0];
                __nv_bfloat162* t1 = (__nv_bfloat162*)&ph[j][1];
                pl[j][0] = packbf2(p0 - __bfloat162float(t0->x), p1 - __bfloat162float(t0->y));
                pl[j][1] = packbf2(p2 - __bfloat162float(t1->x), p3 - __bfloat162float(t1->y));
            }
            rs0 += __shfl_xor_sync(0xffffffffu, rs0, 1);
            rs0 += __shfl_xor_sync(0xffffffffu, rs0, 2);
            rs1 += __shfl_xor_sync(0xffffffffu, rs1, 1);
            rs1 += __shfl_xor_sync(0xffffffffu, rs1, 2);
            l0 = l0 * cr0 + rs0;  l1 = l1 * cr1 + rs1;
            m0 = mn0;  m1 = mn1;
#pragma unroll
            for (int nd = 0; nd < 4; nd++) {
                oacc[nd][0] *= cr0; oacc[nd][1] *= cr0;
                oacc[nd][2] *= cr1; oacc[nd][3] *= cr1;
            }
        }
#pragma unroll
        for (int kk = 0; kk < 4; kk++) {
            uint32_t pa_h[4] = {ph[2 * kk][0], ph[2 * kk][1],
                                ph[2 * kk + 1][0], ph[2 * kk + 1][1]};
            uint32_t pa_l[4] = {pl[2 * kk][0], pl[2 * kk][1],
                                pl[2 * kk + 1][0], pl[2 * kk + 1][1]};
            uint32_t vh[4][2], vl[4][2];
#pragma unroll
            for (int nd2 = 0; nd2 < 2; nd2++) {
                int r = nd2 * 16 + ((lane >> 4) & 1) * 8 + (lane & 7);
                int hh = (kbase >> 3) + 2 * kk + ((lane >> 3) & 1);
                uint32_t t4[4];
                ldmatrix_x4(t4, sb + AVH + r * 528 + hh * 16);
                vh[2 * nd2][0] = t4[0]; vh[2 * nd2][1] = t4[1];
                vh[2 * nd2 + 1][0] = t4[2]; vh[2 * nd2 + 1][1] = t4[3];
                ldmatrix_x4(t4, sb + AVL + r * 528 + hh * 16);
                vl[2 * nd2][0] = t4[0]; vl[2 * nd2][1] = t4[1];
                vl[2 * nd2 + 1][0] = t4[2]; vl[2 * nd2 + 1][1] = t4[3];
            }
            // term-major: same-acc gap = 4
#pragma unroll
            for (int nd = 0; nd < 4; nd++) mma16816(oacc[nd], pa_h, vh[nd]);
#pragma unroll
            for (int nd = 0; nd < 4; nd++) mma16816(oacc[nd], pa_h, vl[nd]);
#pragma unroll
            for (int nd = 0; nd < 4; nd++) mma16816(oacc[nd], pa_l, vh[nd]);
        }
    }

    float inv0 = 1.f / l0, inv1 = 1.f / l1;
    size_t r0 = (size_t)(b * T_) + qb * 128 + wrow + g, r1 = r0 + 8;
#pragma unroll
    for (int nd = 0; nd < 4; nd++) {
        int col = h * 32 + nd * 8 + tg * 2;
        float v00 = oacc[nd][0] * inv0, v01 = oacc[nd][1] * inv0;
        float v10 = oacc[nd][2] * inv1, v11 = oacc[nd][3] * inv1;
        __nv_bfloat16 h00 = __float2bfloat16(v00), h01 = __float2bfloat16(v01);
        __nv_bfloat16 h10 = __float2bfloat16(v10), h11 = __float2bfloat16(v11);
        *(__nv_bfloat162*)(outH + r0 * C_ + col) = __nv_bfloat162(h00, h01);
        *(__nv_bfloat162*)(outH + r1 * C_ + col) = __nv_bfloat162(h10, h11);
        *(__nv_bfloat162*)(outL + r0 * C_ + col) = __nv_bfloat162(
            __float2bfloat16(v00 - __bfloat162float(h00)),
            __float2bfloat16(v01 - __bfloat162float(h01)));
        *(__nv_bfloat162*)(outL + r1 * C_ + col) = __nv_bfloat162(
            __float2bfloat16(v10 - __bfloat162float(h10)),
            __float2bfloat16(v11 - __bfloat162float(h11)));
    }
}

// ---------------- final layernorm ----------------
__global__ void add_ln_kernel(const float* __restrict__ x, const float* __restrict__ w,
                              const float* __restrict__ b,
                              __nv_bfloat16* __restrict__ outH, __nv_bfloat16* __restrict__ outL) {
    const int row = blockIdx.x, c = threadIdx.x;
    float v = x[(size_t)row * C_ + c];
    float s = v, s2 = v * v;
    __shared__ float sh1[8], sh2[8];
#pragma unroll
    for (int o = 16; o; o >>= 1) {
        s  += __shfl_xor_sync(0xffffffffu, s, o);
        s2 += __shfl_xor_sync(0xffffffffu, s2, o);
    }
    if ((c & 31) == 0) { sh1[c >> 5] = s; sh2[c >> 5] = s2; }
    __syncthreads();
    float S = 0.f, Q = 0.f;
#pragma unroll
    for (int i = 0; i < 8; i++) { S += sh1[i]; Q += sh2[i]; }
    float mean = S * (1.f / C_);
    float var  = Q * (1.f / C_) - mean * mean;
    float r = (v - mean) * rsqrtf(var + EPS_) * w[c] + b[c];
    size_t o = (size_t)row * C_ + c;
    __nv_bfloat16 hi = __float2bfloat16(r);
    outH[o] = hi;
    outL[o] = __float2bfloat16(r - __bfloat162float(hi));
}

// ---------------- NLL + loss ----------------
__global__ void nll_kernel(const float* __restrict__ logits, const int* __restrict__ tgt,
                           float* __restrict__ nll) {
    int warp = (blockIdx.x * blockDim.x + threadIdx.x) >> 5;
    int lane = threadIdx.x & 31;
    if (warp >= BT_) return;
    const float* l = logits + (size_t)warp * V_;
    float mx = -INFINITY;
    for (int c = lane; c < V_; c += 32) mx = fmaxf(mx, l[c]);
#pragma unroll
    for (int o = 16; o; o >>= 1) mx = fmaxf(mx, __shfl_xor_sync(0xffffffffu, mx, o));
    float s = 0.f;
    for (int c = lane; c < V_; c += 32) s += __expf(l[c] - mx);
#pragma unroll
    for (int o = 16; o; o >>= 1) s += __shfl_xor_sync(0xffffffffu, s, o);
    if (lane == 0) nll[warp] = -(l[tgt[warp]] - mx - __logf(s));
}
__global__ void reduce_loss_kernel(const float* __restrict__ nll, float* __restrict__ out) {
    __shared__ float sh[256];
    float s = 0.f;
    for (int i = threadIdx.x; i < BT_; i += 256) s += nll[i];
    sh[threadIdx.x] = s;
    __syncthreads();
    for (int st = 128; st; st >>= 1) {
        if (threadIdx.x < st) sh[threadIdx.x] += sh[threadIdx.x + st];
        __syncthreads();
    }
    if (threadIdx.x == 0) *out = sh[0] * (1.f / BT_);
}

// ---------------- host driver (round-6 layout) ----------------
extern "C" void kernel_launch(void* const* d_in, const int* in_sizes, int n_in,
                              void* d_out, int out_size) {
    const int*   idx     = (const int*)  d_in[0];
    const int*   target  = (const int*)  d_in[1];
    const float* tok_emb = (const float*)d_in[2];
    const float* pos_emb = (const float*)d_in[3];
    const float* Wq      = (const float*)d_in[4];
    const float* Wk      = (const float*)d_in[5];
    const float* Wv      = (const float*)d_in[6];
    const float* Wo      = (const float*)d_in[7];
    const float* bo      = (const float*)d_in[8];
    const float* W1      = (const float*)d_in[9];
    const float* b1      = (const float*)d_in[10];
    const float* W2      = (const float*)d_in[11];
    const float* b2_     = (const float*)d_in[12];
    const float* ln1_w   = (const float*)d_in[13];
    const float* ln1_b   = (const float*)d_in[14];
    const float* ln2_w   = (const float*)d_in[15];
    const float* ln2_b   = (const float*)d_in[16];
    const float* lnf_w   = (const float*)d_in[17];
    const float* lnf_b   = (const float*)d_in[18];
    const float* Wlm     = (const float*)d_in[19];
    const float* blm     = (const float*)d_in[20];

    float *px, *pqkv, *pnll;
    __nv_bfloat16 *pxh, *pxl, *pah, *pal, *phh, *phl, *pwh, *pwl;
    cudaGetSymbolAddress((void**)&px,   g_x);
    cudaGetSymbolAddress((void**)&pqkv, g_qkv);
    cudaGetSymbolAddress((void**)&pnll, g_nll);
    cudaGetSymbolAddress((void**)&pxh,  g_xh);
    cudaGetSymbolAddress((void**)&pxl,  g_xl);
    cudaGetSymbolAddress((void**)&pah,  g_ah);
    cudaGetSymbolAddress((void**)&pal,  g_al);
    cudaGetSymbolAddress((void**)&phh,  g_hh);
    cudaGetSymbolAddress((void**)&phl,  g_hl);
    cudaGetSymbolAddress((void**)&pwh,  g_wh);
    cudaGetSymbolAddress((void**)&pwl,  g_wl);

    cudaFuncSetAttribute(flash_attn, cudaFuncAttributeMaxDynamicSharedMemorySize, ATTN_SMEM);
    const int smem256 = 2 * (32768 + 2 * 256 * 128);
    const int smem128 = 2 * (32768 + 2 * 128 * 128);
    cudaFuncSetAttribute(hmma_gemm3<256, 0>, cudaFuncAttributeMaxDynamicSharedMemorySize, smem256);
    cudaFuncSetAttribute(hmma_gemm3<256, 1>, cudaFuncAttributeMaxDynamicSharedMemorySize, smem256);
    cudaFuncSetAttribute(hmma_gemm3<256, 2>, cudaFuncAttributeMaxDynamicSharedMemorySize, smem256);
    cudaFuncSetAttribute(hmma_gemm3<128, 0>, cudaFuncAttributeMaxDynamicSharedMemorySize, smem128);

    convw_all<<<dim3(256, 37), 256>>>(Wq, Wk, Wv, Wo, W1, W2, Wlm, pwh, pwl);
    embed_kernel<<<BT_, C_>>>(idx, tok_emb, pos_emb, px, pxh, pxl);

    const size_t QKV_OSTRIDE = (size_t)BT_ * C_;
    const size_t QKV_WSTRIDE = (size_t)6 * WMAT_ELEMS;

    for (int l = 0; l < L_; l++) {
        hmma_gemm3<256, 0><<<dim3(128, 3), 256, smem256>>>(pxh, pxl,
            pwh + WOFF(0, l), pwl + WOFF(0, l), QKV_WSTRIDE,
            pqkv, QKV_OSTRIDE, nullptr, nullptr, nullptr, nullptr, nullptr, nullptr, C_);
        flash_attn<<<dim3(2, B_ * H_), 256, ATTN_SMEM>>>(pqkv, pah, pal);
        hmma_gemm3<256, 2><<<dim3(128, 1), 256, smem256>>>(pah, pal,
            pwh + WOFF(3, l), pwl + WOFF(3, l), 0,
            px, 0, pxh, pxl, bo + l * C_, px, ln1_w + l * C_, ln1_b + l * C_, C_);
        hmma_gemm3<256, 1><<<dim3(128, 1), 256, smem256>>>(pxh, pxl,
            pwh + WOFF(4, l), pwl + WOFF(4, l), 0,
            nullptr, 0, phh, phl, b1 + l * C_, nullptr, nullptr, nullptr, C_);
        hmma_gemm3<256, 2><<<dim3(128, 1), 256, smem256>>>(phh, phl,
            pwh + WOFF(5, l), pwl + WOFF(5, l), 0,
            px, 0, pxh, pxl, b2_ + l * C_, px, ln2_w + l * C_, ln2_b + l * C_, C_);
    }
    add_ln_kernel<<<BT_, C_>>>(px, lnf_w, lnf_b, pxh, pxl);

    float* logits = (out_size >= BT_ * V_) ? (float*)d_out : pqkv;
    hmma_gemm3<128, 0><<<dim3(128, 1), 256, smem128>>>(pxh, pxl,
        pwh + WOFF_LM, pwl + WOFF_LM, 0,
        logits, 0, nullptr, nullptr, blm, nullptr, nullptr, nullptr, V_);

    nll_kernel<<<(BT_ * 32 + 255) / 256, 256>>>(logits, target, pnll);

    float* loss_dst = nullptr;
    if (out_size == 1)            loss_dst = (float*)d_out;
    else if (out_size > BT_ * V_) loss_dst = (float*)d_out + BT_ * V_;
    if (loss_dst) reduce_loss_kernel<<<1, 256>>>(pnll, loss_dst);
}